// round 11
// baseline (speedup 1.0000x reference)
#include <cuda_runtime.h>
#include <cuda_bf16.h>
#include <math.h>
#include <stdint.h>

#define Bb 8
#define Nn 2048
#define Tt 12
#define Dd 256
#define Hh 8
#define DK 32
#define Mm 8
#define ROWS (Bb * Nn * Tt)          // 196608
#define BN_CNT (Bb * Nn)             // 16384

// Scratch (device globals; allocation-free rule)
__device__ __nv_bfloat16 g_xb[ROWS * Dd];
__device__ __nv_bfloat16 g_qb[ROWS * Dd];
__device__ __nv_bfloat16 g_kb[ROWS * Dd];
__device__ __nv_bfloat16 g_vb[ROWS * Dd];
__device__ __nv_bfloat16 g_ab[ROWS * Dd];
__device__ __nv_bfloat16 g_wq[Dd * Dd];
__device__ __nv_bfloat16 g_wk[Dd * Dd];
__device__ __nv_bfloat16 g_wv[Dd * Dd];
__device__ __nv_bfloat16 g_wf[Dd * Dd];

#define CP_ASYNC16(dst, src) \
    asm volatile("cp.async.cg.shared.global [%0], [%1], 16;" :: "r"(dst), "l"(src))
#define CP_COMMIT() asm volatile("cp.async.commit_group;")
#define CP_WAIT(n)  asm volatile("cp.async.wait_group %0;" :: "n"(n))

#define LDSM_X4(r0, r1, r2, r3, addr) \
    asm volatile("ldmatrix.sync.aligned.m8n8.x4.shared.b16 {%0,%1,%2,%3}, [%4];" \
        : "=r"(r0), "=r"(r1), "=r"(r2), "=r"(r3) : "r"(addr))

__device__ __forceinline__ void mma_bf16(float* c, const unsigned* a, const unsigned* b) {
    asm volatile(
        "mma.sync.aligned.m16n8k16.row.col.f32.bf16.bf16.f32 "
        "{%0,%1,%2,%3}, {%4,%5,%6,%7}, {%8,%9}, {%0,%1,%2,%3};"
        : "+f"(c[0]), "+f"(c[1]), "+f"(c[2]), "+f"(c[3])
        : "r"(a[0]), "r"(a[1]), "r"(a[2]), "r"(a[3]), "r"(b[0]), "r"(b[1]));
}

// ----------------------------------------------------------------------------
// fp32 -> bf16 conversions
// ----------------------------------------------------------------------------
__global__ __launch_bounds__(256) void cvt_kernel(
    const float* __restrict__ in, __nv_bfloat16* __restrict__ out, int n4)
{
    int i = blockIdx.x * 256 + threadIdx.x;
    if (i < n4) {
        float4 v = ((const float4*)in)[i];
        ((__nv_bfloat162*)out)[2 * i]     = __float22bfloat162_rn(make_float2(v.x, v.y));
        ((__nv_bfloat162*)out)[2 * i + 1] = __float22bfloat162_rn(make_float2(v.z, v.w));
    }
}

__global__ __launch_bounds__(256) void cvt_w_kernel(
    const float* __restrict__ w0, const float* __restrict__ w1,
    const float* __restrict__ w2, const float* __restrict__ w3,
    __nv_bfloat16* __restrict__ d0, __nv_bfloat16* __restrict__ d1,
    __nv_bfloat16* __restrict__ d2, __nv_bfloat16* __restrict__ d3)
{
    const int sel = blockIdx.y;
    const float* in = (sel == 0) ? w0 : (sel == 1) ? w1 : (sel == 2) ? w2 : w3;
    __nv_bfloat16* out = (sel == 0) ? d0 : (sel == 1) ? d1 : (sel == 2) ? d2 : d3;
    int i = blockIdx.x * 256 + threadIdx.x;
    float4 v = ((const float4*)in)[i];
    ((__nv_bfloat162*)out)[2 * i]     = __float22bfloat162_rn(make_float2(v.x, v.y));
    ((__nv_bfloat162*)out)[2 * i + 1] = __float22bfloat162_rn(make_float2(v.z, v.w));
}

// ----------------------------------------------------------------------------
// GEMM core (QKV): BM=BN=128, BK=32, 2-stage cp.async, ldmatrix. (R7/R8, proven)
// ----------------------------------------------------------------------------
__device__ __forceinline__ void gemm_core(
    const __nv_bfloat16* __restrict__ A, const __nv_bfloat16* __restrict__ W,
    const float* __restrict__ bias, __nv_bfloat16* __restrict__ Cb, int m0, int n0)
{
    __shared__ __nv_bfloat16 As[2][128][40];
    __shared__ __nv_bfloat16 Bs[2][128][40];

    const int tid  = threadIdx.x;
    const int lane = tid & 31;
    const int wid  = tid >> 5;
    const int wm   = (wid >> 2) * 64;
    const int wn   = (wid & 3) * 32;
    const int g    = lane >> 2;
    const int c    = lane & 3;

    float acc[4][4][4];
    #pragma unroll
    for (int i = 0; i < 4; i++)
        #pragma unroll
        for (int j = 0; j < 4; j++)
            #pragma unroll
            for (int r = 0; r < 4; r++) acc[i][j][r] = 0.f;

    const int idx0 = tid * 2;
    const int r0   = idx0 >> 2;
    const int h0   = (idx0 & 3) << 3;
    const int idx1 = idx0 + 1;
    const int r1   = idx1 >> 2;
    const int h1   = (idx1 & 3) << 3;

    const unsigned sA = (unsigned)__cvta_generic_to_shared(&As[0][0][0]);
    const unsigned sB = (unsigned)__cvta_generic_to_shared(&Bs[0][0][0]);
    const unsigned STG = 128 * 40 * 2;

    auto load_tile = [&](int st, int k0) {
        CP_ASYNC16(sA + st * STG + (r0 * 40 + h0) * 2, &A[(size_t)(m0 + r0) * 256 + k0 + h0]);
        CP_ASYNC16(sB + st * STG + (r0 * 40 + h0) * 2, &W[(size_t)(n0 + r0) * 256 + k0 + h0]);
        CP_ASYNC16(sA + st * STG + (r1 * 40 + h1) * 2, &A[(size_t)(m0 + r1) * 256 + k0 + h1]);
        CP_ASYNC16(sB + st * STG + (r1 * 40 + h1) * 2, &W[(size_t)(n0 + r1) * 256 + k0 + h1]);
    };

    const int arow = lane & 15;
    const int acol = (lane >> 4) << 3;
    const int brow = (lane & 7) + ((lane >> 4) << 3);
    const int bcol = ((lane >> 3) & 1) << 3;

    load_tile(0, 0);  CP_COMMIT();
    load_tile(1, 32); CP_COMMIT();

    #pragma unroll
    for (int kt = 0; kt < 8; kt++) {
        const int st = kt & 1;
        if (kt == 7) { CP_WAIT(0); } else { CP_WAIT(1); }
        __syncthreads();

        #pragma unroll
        for (int kk = 0; kk < 2; kk++) {
            const int kb = kk * 16;
            unsigned af[4][4];
            unsigned bf[4][2];
            #pragma unroll
            for (int im = 0; im < 4; im++) {
                unsigned addr = sA + st * STG +
                    (unsigned)(((wm + im * 16 + arow) * 40 + kb + acol) * 2);
                LDSM_X4(af[im][0], af[im][1], af[im][2], af[im][3], addr);
            }
            #pragma unroll
            for (int np = 0; np < 2; np++) {
                unsigned addr = sB + st * STG +
                    (unsigned)(((wn + np * 16 + brow) * 40 + kb + bcol) * 2);
                LDSM_X4(bf[2 * np][0], bf[2 * np][1], bf[2 * np + 1][0], bf[2 * np + 1][1], addr);
            }
            #pragma unroll
            for (int im = 0; im < 4; im++)
                #pragma unroll
                for (int in_ = 0; in_ < 4; in_++)
                    mma_bf16(acc[im][in_], af[im], bf[in_]);
        }
        __syncthreads();
        if (kt + 2 < 8) { load_tile(st, (kt + 2) * 32); CP_COMMIT(); }
    }

    #pragma unroll
    for (int im = 0; im < 4; im++) {
        int row = m0 + wm + im * 16 + g;
        #pragma unroll
        for (int in_ = 0; in_ < 4; in_++) {
            int col = n0 + wn + in_ * 8 + 2 * c;
            float b0 = bias[col], b1 = bias[col + 1];
            *(__nv_bfloat162*)&Cb[(size_t)row * 256 + col] =
                __float22bfloat162_rn(make_float2(acc[im][in_][0] + b0, acc[im][in_][1] + b1));
            *(__nv_bfloat162*)&Cb[(size_t)(row + 8) * 256 + col] =
                __float22bfloat162_rn(make_float2(acc[im][in_][2] + b0, acc[im][in_][3] + b1));
        }
    }
}

__global__ __launch_bounds__(256) void gemm_qkv_kernel(
    const __nv_bfloat16* __restrict__ xb,
    const __nv_bfloat16* __restrict__ wq, const __nv_bfloat16* __restrict__ wk,
    const __nv_bfloat16* __restrict__ wv,
    const float* __restrict__ bq, const float* __restrict__ bk,
    const float* __restrict__ bv,
    __nv_bfloat16* __restrict__ qb, __nv_bfloat16* __restrict__ kb,
    __nv_bfloat16* __restrict__ vb)
{
    const int sel = blockIdx.y >> 1;
    const int n0  = (blockIdx.y & 1) * 128;
    const __nv_bfloat16* W = (sel == 0) ? wq : (sel == 1) ? wk : wv;
    const float* bias      = (sel == 0) ? bq : (sel == 1) ? bk : bv;
    __nv_bfloat16* C       = (sel == 0) ? qb : (sel == 1) ? kb : vb;
    gemm_core(xb, W, bias, C, blockIdx.x * 128, n0);
}

// ----------------------------------------------------------------------------
// Fused FC GEMM + residual + LayerNorm (R8, proven).
// ----------------------------------------------------------------------------
#define FSTR 24

__global__ __launch_bounds__(256) void gemm_fc_ln_kernel(
    const __nv_bfloat16* __restrict__ A, const __nv_bfloat16* __restrict__ W,
    const float* __restrict__ bias, const float* __restrict__ x,
    const float* __restrict__ gamma, const float* __restrict__ beta,
    float* __restrict__ out)
{
    __shared__ __nv_bfloat16 As[2][128][FSTR];
    __shared__ __nv_bfloat16 Bs[2][256][FSTR];
    __shared__ float psum[8][64];
    __shared__ float psum2[8][64];
    __shared__ float smu[128];
    __shared__ float srstd[128];

    const int tid  = threadIdx.x;
    const int lane = tid & 31;
    const int wid  = tid >> 5;
    const int wm   = (wid >> 2) * 64;
    const int wn   = (wid & 3) * 64;
    const int m0   = blockIdx.x * 128;
    const int g    = lane >> 2;
    const int c    = lane & 3;

    float acc[4][8][4];
    #pragma unroll
    for (int i = 0; i < 4; i++)
        #pragma unroll
        for (int j = 0; j < 8; j++)
            #pragma unroll
            for (int r = 0; r < 4; r++) acc[i][j][r] = 0.f;

    const int rA = tid >> 1;
    const int cC = (tid & 1) << 3;

    const unsigned sA = (unsigned)__cvta_generic_to_shared(&As[0][0][0]);
    const unsigned sB = (unsigned)__cvta_generic_to_shared(&Bs[0][0][0]);
    const unsigned ASTG = 128 * FSTR * 2;
    const unsigned BSTG = 256 * FSTR * 2;

    auto load_tile = [&](int st, int k0) {
        CP_ASYNC16(sA + st * ASTG + (rA * FSTR + cC) * 2,
                   &A[(size_t)(m0 + rA) * 256 + k0 + cC]);
        CP_ASYNC16(sB + st * BSTG + (rA * FSTR + cC) * 2,
                   &W[(size_t)rA * 256 + k0 + cC]);
        CP_ASYNC16(sB + st * BSTG + ((128 + rA) * FSTR + cC) * 2,
                   &W[(size_t)(128 + rA) * 256 + k0 + cC]);
    };

    const int arow = lane & 15;
    const int acol = (lane >> 4) << 3;
    const int brow = (lane & 7) + ((lane >> 4) << 3);
    const int bcol = ((lane >> 3) & 1) << 3;

    load_tile(0, 0);  CP_COMMIT();
    load_tile(1, 16); CP_COMMIT();

    #pragma unroll
    for (int kt = 0; kt < 16; kt++) {
        const int st = kt & 1;
        if (kt == 15) { CP_WAIT(0); } else { CP_WAIT(1); }
        __syncthreads();

        unsigned af[4][4];
        unsigned bf[8][2];
        #pragma unroll
        for (int im = 0; im < 4; im++) {
            unsigned addr = sA + st * ASTG +
                (unsigned)(((wm + im * 16 + arow) * FSTR + acol) * 2);
            LDSM_X4(af[im][0], af[im][1], af[im][2], af[im][3], addr);
        }
        #pragma unroll
        for (int np = 0; np < 4; np++) {
            unsigned addr = sB + st * BSTG +
                (unsigned)(((wn + np * 16 + brow) * FSTR + bcol) * 2);
            LDSM_X4(bf[2 * np][0], bf[2 * np][1], bf[2 * np + 1][0], bf[2 * np + 1][1], addr);
        }
        #pragma unroll
        for (int im = 0; im < 4; im++)
            #pragma unroll
            for (int in_ = 0; in_ < 8; in_++)
                mma_bf16(acc[im][in_], af[im], bf[in_]);

        __syncthreads();
        if (kt + 2 < 16) { load_tile(st, (kt + 2) * 16); CP_COMMIT(); }
    }

    #pragma unroll
    for (int im = 0; im < 4; im++) {
        size_t row  = (size_t)(m0 + wm + im * 16 + g) * 256;
        size_t row2 = row + 8 * 256;
        float s1 = 0.f, q1 = 0.f, s2 = 0.f, q2 = 0.f;
        #pragma unroll
        for (int in_ = 0; in_ < 8; in_++) {
            int col = wn + in_ * 8 + 2 * c;
            float b0 = bias[col], b1 = bias[col + 1];
            float2 x0 = *(const float2*)&x[row + col];
            float2 x1 = *(const float2*)&x[row2 + col];
            float v00 = acc[im][in_][0] + b0 + x0.x;
            float v01 = acc[im][in_][1] + b1 + x0.y;
            float v10 = acc[im][in_][2] + b0 + x1.x;
            float v11 = acc[im][in_][3] + b1 + x1.y;
            acc[im][in_][0] = v00; acc[im][in_][1] = v01;
            acc[im][in_][2] = v10; acc[im][in_][3] = v11;
            s1 += v00 + v01; q1 += v00 * v00 + v01 * v01;
            s2 += v10 + v11; q2 += v10 * v10 + v11 * v11;
        }
        #pragma unroll
        for (int off = 1; off <= 2; off <<= 1) {
            s1 += __shfl_xor_sync(0xffffffffu, s1, off);
            q1 += __shfl_xor_sync(0xffffffffu, q1, off);
            s2 += __shfl_xor_sync(0xffffffffu, s2, off);
            q2 += __shfl_xor_sync(0xffffffffu, q2, off);
        }
        if (c == 0) {
            psum[wid][im * 16 + g]      = s1;
            psum2[wid][im * 16 + g]     = q1;
            psum[wid][im * 16 + g + 8]  = s2;
            psum2[wid][im * 16 + g + 8] = q2;
        }
    }
    __syncthreads();

    if (tid < 128) {
        const int half = tid >> 6;
        const int ri   = tid & 63;
        float s = 0.f, q = 0.f;
        #pragma unroll
        for (int j = 0; j < 4; j++) {
            s += psum[half * 4 + j][ri];
            q += psum2[half * 4 + j][ri];
        }
        float mu  = s * (1.f / 256.f);
        float var = q * (1.f / 256.f) - mu * mu;
        smu[tid]   = mu;
        srstd[tid] = rsqrtf(var + 1e-5f);
    }
    __syncthreads();

    #pragma unroll
    for (int im = 0; im < 4; im++) {
        int rl = wm + im * 16 + g;
        float mu1 = smu[rl],     rs1 = srstd[rl];
        float mu2 = smu[rl + 8], rs2 = srstd[rl + 8];
        size_t row  = (size_t)(m0 + rl) * 256;
        size_t row2 = row + 8 * 256;
        #pragma unroll
        for (int in_ = 0; in_ < 8; in_++) {
            int col = wn + in_ * 8 + 2 * c;
            float ga0 = gamma[col], ga1 = gamma[col + 1];
            float be0 = beta[col],  be1 = beta[col + 1];
            *(float2*)&out[row + col] = make_float2(
                (acc[im][in_][0] - mu1) * rs1 * ga0 + be0,
                (acc[im][in_][1] - mu1) * rs1 * ga1 + be1);
            *(float2*)&out[row2 + col] = make_float2(
                (acc[im][in_][2] - mu2) * rs2 * ga0 + be0,
                (acc[im][in_][3] - mu2) * rs2 * ga1 + be1);
        }
    }
}

// ----------------------------------------------------------------------------
// Attention v5b: all-bf16, pad columns ZEROED (fix for R10 NaN).
// ----------------------------------------------------------------------------
#define QK_STR 264    // halfs per Q/K smem row
#define BV_STR 40     // halfs per Bv row (32 used + 8 pad)
#define P_STR  40     // halfs per P row

__global__ __launch_bounds__(256) void attn_kernel(
    const __nv_bfloat16* __restrict__ Q, const __nv_bfloat16* __restrict__ K,
    const __nv_bfloat16* __restrict__ V,
    const float* __restrict__ mem_k, const float* __restrict__ mem_v,
    const float* __restrict__ alpha_l, __nv_bfloat16* __restrict__ out)
{
    __shared__ __nv_bfloat16 Qs[Tt * QK_STR];
    __shared__ __nv_bfloat16 Ks[Tt * QK_STR];
    __shared__ __nv_bfloat16 Bv[256 * BV_STR];
    __shared__ __nv_bfloat16 Ps[Hh][16 * P_STR];

    const int tid  = threadIdx.x;
    const int lane = tid & 31;
    const int h    = tid >> 5;
    const int g    = lane >> 2;
    const int c    = lane & 3;
    const int hc   = h * DK;
    const size_t base = (size_t)blockIdx.x * (Tt * Dd);

    // stage Q,K raw; V transposed into Bv cols 0..11
    for (int i = tid; i < Tt * 32; i += 256) {
        int r = i >> 5, c8 = (i & 31) * 8;
        *(uint4*)&Qs[r * QK_STR + c8] = *(const uint4*)&Q[base + r * 256 + c8];
        *(uint4*)&Ks[r * QK_STR + c8] = *(const uint4*)&K[base + r * 256 + c8];
        uint4 vu = *(const uint4*)&V[base + r * 256 + c8];
        const __nv_bfloat16* vh = (const __nv_bfloat16*)&vu;
        #pragma unroll
        for (int j = 0; j < 8; j++)
            Bv[(c8 + j) * BV_STR + r] = vh[j];
    }
    // FIX (R10 NaN): zero Bv pad columns 12..15 and 24..39 for every row.
    // MMA k-steps read cols 0..31; P pads are zero but 0*garbage(NaN/Inf)=NaN.
    #pragma unroll
    for (int ii = 0; ii < 10; ii++) {
        int i = ii * 256 + tid;            // 0..2559
        int row = i / 10, j = i % 10;
        int off = (j < 2) ? (12 + 2 * j) : (24 + 2 * (j - 2));
        *(uint32_t*)&Bv[row * BV_STR + off] = 0u;
    }
    // mem_v into Bv cols 16..23 (warp h handles head h; lane = dk)
    #pragma unroll
    for (int m = 0; m < Mm; m++)
        Bv[(hc + lane) * BV_STR + 16 + m] =
            __float2bfloat16_rn(mem_v[(h * Mm + m) * DK + lane]);
    // zero P region for this head (covers pad cols/rows)
    {
        uint32_t* pz = (uint32_t*)Ps[h];
        #pragma unroll
        for (int i = 0; i < 10; i++) pz[lane + i * 32] = 0u;
    }
    __syncthreads();

    // ---- scores via bf16 MMA: S0 (s 0..7), S1 (s 8..15), Sm (m 0..7) ----
    float s0[4] = {0.f, 0.f, 0.f, 0.f};
    float s1[4] = {0.f, 0.f, 0.f, 0.f};
    float sm[4] = {0.f, 0.f, 0.f, 0.f};
    #pragma unroll
    for (int kk = 0; kk < 2; kk++) {
        const int kb = hc + kk * 16;
        unsigned a[4];
        a[0] = *(const unsigned*)&Qs[g * QK_STR + kb + 2 * c];
        a[1] = (g < 4) ? *(const unsigned*)&Qs[(g + 8) * QK_STR + kb + 2 * c] : 0u;
        a[2] = *(const unsigned*)&Qs[g * QK_STR + kb + 2 * c + 8];
        a[3] = (g < 4) ? *(const unsigned*)&Qs[(g + 8) * QK_STR + kb + 2 * c + 8] : 0u;
        unsigned b0[2], b1[2], bm[2];
        b0[0] = *(const unsigned*)&Ks[g * QK_STR + kb + 2 * c];
        b0[1] = *(const unsigned*)&Ks[g * QK_STR + kb + 2 * c + 8];
        b1[0] = (g < 4) ? *(const unsigned*)&Ks[(g + 8) * QK_STR + kb + 2 * c] : 0u;
        b1[1] = (g < 4) ? *(const unsigned*)&Ks[(g + 8) * QK_STR + kb + 2 * c + 8] : 0u;
        float2 mk0 = *(const float2*)&mem_k[(h * Mm + g) * DK + kk * 16 + 2 * c];
        float2 mk1 = *(const float2*)&mem_k[(h * Mm + g) * DK + kk * 16 + 2 * c + 8];
        __nv_bfloat162 mkb0 = __float22bfloat162_rn(mk0);
        __nv_bfloat162 mkb1 = __float22bfloat162_rn(mk1);
        bm[0] = *(const unsigned*)&mkb0;
        bm[1] = *(const unsigned*)&mkb1;
        mma_bf16(s0, a, b0);
        mma_bf16(s1, a, b1);
        mma_bf16(sm, a, bm);
    }

    // ---- causal mask + scale ----
    const float scale = 0.1767766952966369f;
    const int s00 = 2 * c, s01 = 2 * c + 1, s10 = 8 + 2 * c, s11 = 8 + 2 * c + 1;
    const int tlo = g, thi = g + 8;
    float e[8];
    e[0] = (s00 <= tlo) ? s0[0] * scale : -1e30f;
    e[1] = (s01 <= tlo) ? s0[1] * scale : -1e30f;
    e[2] = (s10 <= tlo) ? s1[0] * scale : -1e30f;
    e[3] = (s11 <= tlo) ? s1[1] * scale : -1e30f;
    e[4] = (s00 <= thi) ? s0[2] * scale : -1e30f;
    e[5] = (s01 <= thi) ? s0[3] * scale : -1e30f;
    e[6] = (s10 <= thi) ? s1[2] * scale : -1e30f;
    e[7] = (s11 <= thi) ? s1[3] * scale : -1e30f;

    // ---- time softmax (row lives in one quad: 2-step shfl) ----
    float mlo = fmaxf(fmaxf(e[0], e[1]), fmaxf(e[2], e[3]));
    float mhi = fmaxf(fmaxf(e[4], e[5]), fmaxf(e[6], e[7]));
    mlo = fmaxf(mlo, __shfl_xor_sync(0xffffffffu, mlo, 1));
    mlo = fmaxf(mlo, __shfl_xor_sync(0xffffffffu, mlo, 2));
    mhi = fmaxf(mhi, __shfl_xor_sync(0xffffffffu, mhi, 1));
    mhi = fmaxf(mhi, __shfl_xor_sync(0xffffffffu, mhi, 2));
    #pragma unroll
    for (int j = 0; j < 4; j++) e[j] = __expf(e[j] - mlo);
    #pragma unroll
    for (int j = 4; j < 8; j++) e[j] = __expf(e[j] - mhi);
    float slo = e[0] + e[1] + e[2] + e[3];
    float shi = e[4] + e[5] + e[6] + e[7];
    slo += __shfl_xor_sync(0xffffffffu, slo, 1);
    slo += __shfl_xor_sync(0xffffffffu, slo, 2);
    shi += __shfl_xor_sync(0xffffffffu, shi, 1);
    shi += __shfl_xor_sync(0xffffffffu, shi, 2);
    float rlo = 1.f / slo, rhi = 1.f / shi;
    #pragma unroll
    for (int j = 0; j < 4; j++) e[j] *= rlo;
    #pragma unroll
    for (int j = 4; j < 8; j++) e[j] *= rhi;

    // ---- memory softmax ----
    float em[4];
    em[0] = sm[0] * scale; em[1] = sm[1] * scale;
    em[2] = sm[2] * scale; em[3] = sm[3] * scale;
    float mmlo = fmaxf(em[0], em[1]);
    float mmhi = fmaxf(em[2], em[3]);
    mmlo = fmaxf(mmlo, __shfl_xor_sync(0xffffffffu, mmlo, 1));
    mmlo = fmaxf(mmlo, __shfl_xor_sync(0xffffffffu, mmlo, 2));
    mmhi = fmaxf(mmhi, __shfl_xor_sync(0xffffffffu, mmhi, 1));
    mmhi = fmaxf(mmhi, __shfl_xor_sync(0xffffffffu, mmhi, 2));
    em[0] = __expf(em[0] - mmlo); em[1] = __expf(em[1] - mmlo);
    em[2] = __expf(em[2] - mmhi); em[3] = __expf(em[3] - mmhi);
    float smlo = em[0] + em[1];
    float smhi = em[2] + em[3];
    smlo += __shfl_xor_sync(0xffffffffu, smlo, 1);
    smlo += __shfl_xor_sync(0xffffffffu, smlo, 2);
    smhi += __shfl_xor_sync(0xffffffffu, smhi, 1);
    smhi += __shfl_xor_sync(0xffffffffu, smhi, 2);
    em[0] *= 1.f / smlo; em[1] *= 1.f / smlo;
    em[2] *= 1.f / smhi; em[3] *= 1.f / smhi;

    // ---- stage gate-scaled P (bf16): time cols 0..11, mem cols 16..23 ----
    const float wl = 1.f / (1.f + __expf(-alpha_l[0]));
    const float wt = 1.f - wl;
    __nv_bfloat16* Pw = Ps[h];
    Pw[tlo * P_STR + s00] = __float2bfloat16_rn(wt * e[0]);
    Pw[tlo * P_STR + s01] = __float2bfloat16_rn(wt * e[1]);
    Pw[tlo * P_STR + s10] = __float2bfloat16_rn(wt * e[2]);
    Pw[tlo * P_STR + s11] = __float2bfloat16_rn(wt * e[3]);
    Pw[tlo * P_STR + 16 + s00] = __float2bfloat16_rn(wl * em[0]);
    Pw[tlo * P_STR + 16 + s01] = __float2bfloat16_rn(wl * em[1]);
    if (g < 4) {
        Pw[thi * P_STR + s00] = __float2bfloat16_rn(wt * e[4]);
        Pw[thi * P_STR + s01] = __float2bfloat16_rn(wt * e[5]);
        Pw[thi * P_STR + s10] = __float2bfloat16_rn(wt * e[6]);
        Pw[thi * P_STR + s11] = __float2bfloat16_rn(wt * e[7]);
        Pw[thi * P_STR + 16 + s00] = __float2bfloat16_rn(wl * em[2]);
        Pw[thi * P_STR + 16 + s01] = __float2bfloat16_rn(wl * em[3]);
    }
    __syncwarp();

    // ---- O = [P | Pm] . [V ; mem_v^T]  (K=32, 2 k-steps x 4 n-tiles) ----
    float o[4][4];
    #pragma unroll
    for (int nt = 0; nt < 4; nt++)
        #pragma unroll
        for (int r = 0; r < 4; r++) o[nt][r] = 0.f;

    #pragma unroll
    for (int kk = 0; kk < 2; kk++) {
        const int kb = kk * 16;
        unsigned pa[4];
        pa[0] = *(const unsigned*)&Pw[g * P_STR + kb + 2 * c];
        pa[1] = (g < 4) ? *(const unsigned*)&Pw[(g + 8) * P_STR + kb + 2 * c] : 0u;
        pa[2] = *(const unsigned*)&Pw[g * P_STR + kb + 2 * c + 8];
        pa[3] = (g < 4) ? *(const unsigned*)&Pw[(g + 8) * P_STR + kb + 2 * c + 8] : 0u;
        #pragma unroll
        for (int nt = 0; nt < 4; nt++) {
            const int n = hc + nt * 8 + g;
            unsigned vb2[2];
            vb2[0] = *(const unsigned*)&Bv[n * BV_STR + kb + 2 * c];
            vb2[1] = *(const unsigned*)&Bv[n * BV_STR + kb + 2 * c + 8];
            mma_bf16(o[nt], pa, vb2);
        }
    }

    // ---- store (already gated) ----
    #pragma unroll
    for (int nt = 0; nt < 4; nt++) {
        int col = hc + nt * 8 + 2 * c;
        *(__nv_bfloat162*)&out[base + tlo * 256 + col] =
            __float22bfloat162_rn(make_float2(o[nt][0], o[nt][1]));
        if (g < 4) {
            *(__nv_bfloat162*)&out[base + thi * 256 + col] =
                __float22bfloat162_rn(make_float2(o[nt][2], o[nt][3]));
        }
    }
}

// ----------------------------------------------------------------------------
// Launch
// ----------------------------------------------------------------------------
extern "C" void kernel_launch(void* const* d_in, const int* in_sizes, int n_in,
                              void* d_out, int out_size)
{
    const float* x     = (const float*)d_in[0];
    const float* Wq_w  = (const float*)d_in[1];
    const float* Wq_b  = (const float*)d_in[2];
    const float* Wk_w  = (const float*)d_in[3];
    const float* Wk_b  = (const float*)d_in[4];
    const float* Wv_w  = (const float*)d_in[5];
    const float* Wv_b  = (const float*)d_in[6];
    const float* mem_k = (const float*)d_in[7];
    const float* mem_v = (const float*)d_in[8];
    const float* fc_w  = (const float*)d_in[9];
    const float* fc_b  = (const float*)d_in[10];
    const float* gamma = (const float*)d_in[11];
    const float* beta  = (const float*)d_in[12];
    const float* alpha = (const float*)d_in[13];
    float* out = (float*)d_out;

    __nv_bfloat16 *xb, *qb, *kb, *vb, *ab, *wq, *wk, *wv, *wf;
    cudaGetSymbolAddress((void**)&xb, g_xb);
    cudaGetSymbolAddress((void**)&qb, g_qb);
    cudaGetSymbolAddress((void**)&kb, g_kb);
    cudaGetSymbolAddress((void**)&vb, g_vb);
    cudaGetSymbolAddress((void**)&ab, g_ab);
    cudaGetSymbolAddress((void**)&wq, g_wq);
    cudaGetSymbolAddress((void**)&wk, g_wk);
    cudaGetSymbolAddress((void**)&wv, g_wv);
    cudaGetSymbolAddress((void**)&wf, g_wf);

    const int xn4 = ROWS * Dd / 4;
    cvt_kernel<<<(xn4 + 255) / 256, 256>>>(x, xb, xn4);
    dim3 wgrid(64, 4);
    cvt_w_kernel<<<wgrid, 256>>>(Wq_w, Wk_w, Wv_w, fc_w, wq, wk, wv, wf);

    dim3 qkv_grid(ROWS / 128, 6);
    gemm_qkv_kernel<<<qkv_grid, 256>>>(xb, wq, wk, wv, Wq_b, Wk_b, Wv_b, qb, kb, vb);

    attn_kernel<<<BN_CNT, 256>>>(qb, kb, vb, mem_k, mem_v, alpha, ab);

    gemm_fc_ln_kernel<<<ROWS / 128, 256>>>(ab, wf, fc_b, x, gamma, beta, out);
}

// round 12
// speedup vs baseline: 1.2166x; 1.2166x over previous
#include <cuda_runtime.h>
#include <cuda_bf16.h>
#include <math.h>
#include <stdint.h>

#define Bb 8
#define Nn 2048
#define Tt 12
#define Dd 256
#define Hh 8
#define DK 32
#define Mm 8
#define ROWS (Bb * Nn * Tt)          // 196608
#define BN_CNT (Bb * Nn)             // 16384

// Scratch (device globals; allocation-free rule)
__device__ __nv_bfloat16 g_xb[ROWS * Dd];
__device__ __nv_bfloat16 g_qb[ROWS * Dd];
__device__ __nv_bfloat16 g_kb[ROWS * Dd];
__device__ __nv_bfloat16 g_vb[ROWS * Dd];
__device__ __nv_bfloat16 g_ab[ROWS * Dd];
__device__ __nv_bfloat16 g_wq[Dd * Dd];
__device__ __nv_bfloat16 g_wk[Dd * Dd];
__device__ __nv_bfloat16 g_wv[Dd * Dd];
__device__ __nv_bfloat16 g_wf[Dd * Dd];

#define CP_ASYNC16(dst, src) \
    asm volatile("cp.async.cg.shared.global [%0], [%1], 16;" :: "r"(dst), "l"(src))
#define CP_COMMIT() asm volatile("cp.async.commit_group;")
#define CP_WAIT(n)  asm volatile("cp.async.wait_group %0;" :: "n"(n))

#define LDSM_X4(r0, r1, r2, r3, addr) \
    asm volatile("ldmatrix.sync.aligned.m8n8.x4.shared.b16 {%0,%1,%2,%3}, [%4];" \
        : "=r"(r0), "=r"(r1), "=r"(r2), "=r"(r3) : "r"(addr))

#define LDSM_X4_T(r0, r1, r2, r3, addr) \
    asm volatile("ldmatrix.sync.aligned.m8n8.x4.trans.shared.b16 {%0,%1,%2,%3}, [%4];" \
        : "=r"(r0), "=r"(r1), "=r"(r2), "=r"(r3) : "r"(addr))

__device__ __forceinline__ void mma_bf16(float* c, const unsigned* a, const unsigned* b) {
    asm volatile(
        "mma.sync.aligned.m16n8k16.row.col.f32.bf16.bf16.f32 "
        "{%0,%1,%2,%3}, {%4,%5,%6,%7}, {%8,%9}, {%0,%1,%2,%3};"
        : "+f"(c[0]), "+f"(c[1]), "+f"(c[2]), "+f"(c[3])
        : "r"(a[0]), "r"(a[1]), "r"(a[2]), "r"(a[3]), "r"(b[0]), "r"(b[1]));
}

// ----------------------------------------------------------------------------
// fp32 -> bf16 conversions
// ----------------------------------------------------------------------------
__global__ __launch_bounds__(256) void cvt_kernel(
    const float* __restrict__ in, __nv_bfloat16* __restrict__ out, int n4)
{
    int i = blockIdx.x * 256 + threadIdx.x;
    if (i < n4) {
        float4 v = ((const float4*)in)[i];
        ((__nv_bfloat162*)out)[2 * i]     = __float22bfloat162_rn(make_float2(v.x, v.y));
        ((__nv_bfloat162*)out)[2 * i + 1] = __float22bfloat162_rn(make_float2(v.z, v.w));
    }
}

__global__ __launch_bounds__(256) void cvt_w_kernel(
    const float* __restrict__ w0, const float* __restrict__ w1,
    const float* __restrict__ w2, const float* __restrict__ w3,
    __nv_bfloat16* __restrict__ d0, __nv_bfloat16* __restrict__ d1,
    __nv_bfloat16* __restrict__ d2, __nv_bfloat16* __restrict__ d3)
{
    const int sel = blockIdx.y;
    const float* in = (sel == 0) ? w0 : (sel == 1) ? w1 : (sel == 2) ? w2 : w3;
    __nv_bfloat16* out = (sel == 0) ? d0 : (sel == 1) ? d1 : (sel == 2) ? d2 : d3;
    int i = blockIdx.x * 256 + threadIdx.x;
    float4 v = ((const float4*)in)[i];
    ((__nv_bfloat162*)out)[2 * i]     = __float22bfloat162_rn(make_float2(v.x, v.y));
    ((__nv_bfloat162*)out)[2 * i + 1] = __float22bfloat162_rn(make_float2(v.z, v.w));
}

// ----------------------------------------------------------------------------
// GEMM core (QKV): BM=BN=128, BK=32, 2-stage cp.async, ldmatrix. (R7/R8, proven)
// ----------------------------------------------------------------------------
__device__ __forceinline__ void gemm_core(
    const __nv_bfloat16* __restrict__ A, const __nv_bfloat16* __restrict__ W,
    const float* __restrict__ bias, __nv_bfloat16* __restrict__ Cb, int m0, int n0)
{
    __shared__ __nv_bfloat16 As[2][128][40];
    __shared__ __nv_bfloat16 Bs[2][128][40];

    const int tid  = threadIdx.x;
    const int lane = tid & 31;
    const int wid  = tid >> 5;
    const int wm   = (wid >> 2) * 64;
    const int wn   = (wid & 3) * 32;
    const int g    = lane >> 2;
    const int c    = lane & 3;

    float acc[4][4][4];
    #pragma unroll
    for (int i = 0; i < 4; i++)
        #pragma unroll
        for (int j = 0; j < 4; j++)
            #pragma unroll
            for (int r = 0; r < 4; r++) acc[i][j][r] = 0.f;

    const int idx0 = tid * 2;
    const int r0   = idx0 >> 2;
    const int h0   = (idx0 & 3) << 3;
    const int idx1 = idx0 + 1;
    const int r1   = idx1 >> 2;
    const int h1   = (idx1 & 3) << 3;

    const unsigned sA = (unsigned)__cvta_generic_to_shared(&As[0][0][0]);
    const unsigned sB = (unsigned)__cvta_generic_to_shared(&Bs[0][0][0]);
    const unsigned STG = 128 * 40 * 2;

    auto load_tile = [&](int st, int k0) {
        CP_ASYNC16(sA + st * STG + (r0 * 40 + h0) * 2, &A[(size_t)(m0 + r0) * 256 + k0 + h0]);
        CP_ASYNC16(sB + st * STG + (r0 * 40 + h0) * 2, &W[(size_t)(n0 + r0) * 256 + k0 + h0]);
        CP_ASYNC16(sA + st * STG + (r1 * 40 + h1) * 2, &A[(size_t)(m0 + r1) * 256 + k0 + h1]);
        CP_ASYNC16(sB + st * STG + (r1 * 40 + h1) * 2, &W[(size_t)(n0 + r1) * 256 + k0 + h1]);
    };

    const int arow = lane & 15;
    const int acol = (lane >> 4) << 3;
    const int brow = (lane & 7) + ((lane >> 4) << 3);
    const int bcol = ((lane >> 3) & 1) << 3;

    load_tile(0, 0);  CP_COMMIT();
    load_tile(1, 32); CP_COMMIT();

    #pragma unroll
    for (int kt = 0; kt < 8; kt++) {
        const int st = kt & 1;
        if (kt == 7) { CP_WAIT(0); } else { CP_WAIT(1); }
        __syncthreads();

        #pragma unroll
        for (int kk = 0; kk < 2; kk++) {
            const int kb = kk * 16;
            unsigned af[4][4];
            unsigned bf[4][2];
            #pragma unroll
            for (int im = 0; im < 4; im++) {
                unsigned addr = sA + st * STG +
                    (unsigned)(((wm + im * 16 + arow) * 40 + kb + acol) * 2);
                LDSM_X4(af[im][0], af[im][1], af[im][2], af[im][3], addr);
            }
            #pragma unroll
            for (int np = 0; np < 2; np++) {
                unsigned addr = sB + st * STG +
                    (unsigned)(((wn + np * 16 + brow) * 40 + kb + bcol) * 2);
                LDSM_X4(bf[2 * np][0], bf[2 * np][1], bf[2 * np + 1][0], bf[2 * np + 1][1], addr);
            }
            #pragma unroll
            for (int im = 0; im < 4; im++)
                #pragma unroll
                for (int in_ = 0; in_ < 4; in_++)
                    mma_bf16(acc[im][in_], af[im], bf[in_]);
        }
        __syncthreads();
        if (kt + 2 < 8) { load_tile(st, (kt + 2) * 32); CP_COMMIT(); }
    }

    #pragma unroll
    for (int im = 0; im < 4; im++) {
        int row = m0 + wm + im * 16 + g;
        #pragma unroll
        for (int in_ = 0; in_ < 4; in_++) {
            int col = n0 + wn + in_ * 8 + 2 * c;
            float b0 = bias[col], b1 = bias[col + 1];
            *(__nv_bfloat162*)&Cb[(size_t)row * 256 + col] =
                __float22bfloat162_rn(make_float2(acc[im][in_][0] + b0, acc[im][in_][1] + b1));
            *(__nv_bfloat162*)&Cb[(size_t)(row + 8) * 256 + col] =
                __float22bfloat162_rn(make_float2(acc[im][in_][2] + b0, acc[im][in_][3] + b1));
        }
    }
}

__global__ __launch_bounds__(256) void gemm_qkv_kernel(
    const __nv_bfloat16* __restrict__ xb,
    const __nv_bfloat16* __restrict__ wq, const __nv_bfloat16* __restrict__ wk,
    const __nv_bfloat16* __restrict__ wv,
    const float* __restrict__ bq, const float* __restrict__ bk,
    const float* __restrict__ bv,
    __nv_bfloat16* __restrict__ qb, __nv_bfloat16* __restrict__ kb,
    __nv_bfloat16* __restrict__ vb)
{
    const int sel = blockIdx.y >> 1;
    const int n0  = (blockIdx.y & 1) * 128;
    const __nv_bfloat16* W = (sel == 0) ? wq : (sel == 1) ? wk : wv;
    const float* bias      = (sel == 0) ? bq : (sel == 1) ? bk : bv;
    __nv_bfloat16* C       = (sel == 0) ? qb : (sel == 1) ? kb : vb;
    gemm_core(xb, W, bias, C, blockIdx.x * 128, n0);
}

// ----------------------------------------------------------------------------
// Fused FC GEMM + residual + LayerNorm (R8, proven).
// ----------------------------------------------------------------------------
#define FSTR 24

__global__ __launch_bounds__(256) void gemm_fc_ln_kernel(
    const __nv_bfloat16* __restrict__ A, const __nv_bfloat16* __restrict__ W,
    const float* __restrict__ bias, const float* __restrict__ x,
    const float* __restrict__ gamma, const float* __restrict__ beta,
    float* __restrict__ out)
{
    __shared__ __nv_bfloat16 As[2][128][FSTR];
    __shared__ __nv_bfloat16 Bs[2][256][FSTR];
    __shared__ float psum[8][64];
    __shared__ float psum2[8][64];
    __shared__ float smu[128];
    __shared__ float srstd[128];

    const int tid  = threadIdx.x;
    const int lane = tid & 31;
    const int wid  = tid >> 5;
    const int wm   = (wid >> 2) * 64;
    const int wn   = (wid & 3) * 64;
    const int m0   = blockIdx.x * 128;
    const int g    = lane >> 2;
    const int c    = lane & 3;

    float acc[4][8][4];
    #pragma unroll
    for (int i = 0; i < 4; i++)
        #pragma unroll
        for (int j = 0; j < 8; j++)
            #pragma unroll
            for (int r = 0; r < 4; r++) acc[i][j][r] = 0.f;

    const int rA = tid >> 1;
    const int cC = (tid & 1) << 3;

    const unsigned sA = (unsigned)__cvta_generic_to_shared(&As[0][0][0]);
    const unsigned sB = (unsigned)__cvta_generic_to_shared(&Bs[0][0][0]);
    const unsigned ASTG = 128 * FSTR * 2;
    const unsigned BSTG = 256 * FSTR * 2;

    auto load_tile = [&](int st, int k0) {
        CP_ASYNC16(sA + st * ASTG + (rA * FSTR + cC) * 2,
                   &A[(size_t)(m0 + rA) * 256 + k0 + cC]);
        CP_ASYNC16(sB + st * BSTG + (rA * FSTR + cC) * 2,
                   &W[(size_t)rA * 256 + k0 + cC]);
        CP_ASYNC16(sB + st * BSTG + ((128 + rA) * FSTR + cC) * 2,
                   &W[(size_t)(128 + rA) * 256 + k0 + cC]);
    };

    const int arow = lane & 15;
    const int acol = (lane >> 4) << 3;
    const int brow = (lane & 7) + ((lane >> 4) << 3);
    const int bcol = ((lane >> 3) & 1) << 3;

    load_tile(0, 0);  CP_COMMIT();
    load_tile(1, 16); CP_COMMIT();

    #pragma unroll
    for (int kt = 0; kt < 16; kt++) {
        const int st = kt & 1;
        if (kt == 15) { CP_WAIT(0); } else { CP_WAIT(1); }
        __syncthreads();

        unsigned af[4][4];
        unsigned bf[8][2];
        #pragma unroll
        for (int im = 0; im < 4; im++) {
            unsigned addr = sA + st * ASTG +
                (unsigned)(((wm + im * 16 + arow) * FSTR + acol) * 2);
            LDSM_X4(af[im][0], af[im][1], af[im][2], af[im][3], addr);
        }
        #pragma unroll
        for (int np = 0; np < 4; np++) {
            unsigned addr = sB + st * BSTG +
                (unsigned)(((wn + np * 16 + brow) * FSTR + bcol) * 2);
            LDSM_X4(bf[2 * np][0], bf[2 * np][1], bf[2 * np + 1][0], bf[2 * np + 1][1], addr);
        }
        #pragma unroll
        for (int im = 0; im < 4; im++)
            #pragma unroll
            for (int in_ = 0; in_ < 8; in_++)
                mma_bf16(acc[im][in_], af[im], bf[in_]);

        __syncthreads();
        if (kt + 2 < 16) { load_tile(st, (kt + 2) * 16); CP_COMMIT(); }
    }

    #pragma unroll
    for (int im = 0; im < 4; im++) {
        size_t row  = (size_t)(m0 + wm + im * 16 + g) * 256;
        size_t row2 = row + 8 * 256;
        float s1 = 0.f, q1 = 0.f, s2 = 0.f, q2 = 0.f;
        #pragma unroll
        for (int in_ = 0; in_ < 8; in_++) {
            int col = wn + in_ * 8 + 2 * c;
            float b0 = bias[col], b1 = bias[col + 1];
            float2 x0 = *(const float2*)&x[row + col];
            float2 x1 = *(const float2*)&x[row2 + col];
            float v00 = acc[im][in_][0] + b0 + x0.x;
            float v01 = acc[im][in_][1] + b1 + x0.y;
            float v10 = acc[im][in_][2] + b0 + x1.x;
            float v11 = acc[im][in_][3] + b1 + x1.y;
            acc[im][in_][0] = v00; acc[im][in_][1] = v01;
            acc[im][in_][2] = v10; acc[im][in_][3] = v11;
            s1 += v00 + v01; q1 += v00 * v00 + v01 * v01;
            s2 += v10 + v11; q2 += v10 * v10 + v11 * v11;
        }
        #pragma unroll
        for (int off = 1; off <= 2; off <<= 1) {
            s1 += __shfl_xor_sync(0xffffffffu, s1, off);
            q1 += __shfl_xor_sync(0xffffffffu, q1, off);
            s2 += __shfl_xor_sync(0xffffffffu, s2, off);
            q2 += __shfl_xor_sync(0xffffffffu, q2, off);
        }
        if (c == 0) {
            psum[wid][im * 16 + g]      = s1;
            psum2[wid][im * 16 + g]     = q1;
            psum[wid][im * 16 + g + 8]  = s2;
            psum2[wid][im * 16 + g + 8] = q2;
        }
    }
    __syncthreads();

    if (tid < 128) {
        const int half = tid >> 6;
        const int ri   = tid & 63;
        float s = 0.f, q = 0.f;
        #pragma unroll
        for (int j = 0; j < 4; j++) {
            s += psum[half * 4 + j][ri];
            q += psum2[half * 4 + j][ri];
        }
        float mu  = s * (1.f / 256.f);
        float var = q * (1.f / 256.f) - mu * mu;
        smu[tid]   = mu;
        srstd[tid] = rsqrtf(var + 1e-5f);
    }
    __syncthreads();

    #pragma unroll
    for (int im = 0; im < 4; im++) {
        int rl = wm + im * 16 + g;
        float mu1 = smu[rl],     rs1 = srstd[rl];
        float mu2 = smu[rl + 8], rs2 = srstd[rl + 8];
        size_t row  = (size_t)(m0 + rl) * 256;
        size_t row2 = row + 8 * 256;
        #pragma unroll
        for (int in_ = 0; in_ < 8; in_++) {
            int col = wn + in_ * 8 + 2 * c;
            float ga0 = gamma[col], ga1 = gamma[col + 1];
            float be0 = beta[col],  be1 = beta[col + 1];
            *(float2*)&out[row + col] = make_float2(
                (acc[im][in_][0] - mu1) * rs1 * ga0 + be0,
                (acc[im][in_][1] - mu1) * rs1 * ga1 + be1);
            *(float2*)&out[row2 + col] = make_float2(
                (acc[im][in_][2] - mu2) * rs2 * ga0 + be0,
                (acc[im][in_][3] - mu2) * rs2 * ga1 + be1);
        }
    }
}

// ----------------------------------------------------------------------------
// Attention v6: all-bf16, all fragments via ldmatrix (trans for V).
// Smem (dynamic): Qs[16][264], Ks[32][264] (rows 16-23 = mem_k per head),
// Vc[32][264] (rows 16-23 = mem_v per head), Ps[8][16][40].
// Pad rows zeroed. One block per bn; warp h = head h.
// ----------------------------------------------------------------------------
#define ASTR 264
#define P_STR 40
#define ATTN_SMEM ((80 * ASTR + Hh * 16 * P_STR) * 2)   // 52480 bytes

__global__ __launch_bounds__(256) void attn_kernel(
    const __nv_bfloat16* __restrict__ Q, const __nv_bfloat16* __restrict__ K,
    const __nv_bfloat16* __restrict__ V,
    const float* __restrict__ mem_k, const float* __restrict__ mem_v,
    const float* __restrict__ alpha_l, __nv_bfloat16* __restrict__ out)
{
    extern __shared__ __nv_bfloat16 smem_attn[];
    __nv_bfloat16* Qs = smem_attn;              // 16 rows
    __nv_bfloat16* Ks = smem_attn + 16 * ASTR;  // 32 rows
    __nv_bfloat16* Vc = smem_attn + 48 * ASTR;  // 32 rows

    const int tid  = threadIdx.x;
    const int lane = tid & 31;
    const int h    = tid >> 5;
    const int g    = lane >> 2;
    const int c    = lane & 3;
    const int hc   = h * DK;
    const size_t base = (size_t)blockIdx.x * (Tt * Dd);

    __nv_bfloat16* Ph = smem_attn + 80 * ASTR + h * (16 * P_STR);

    // stage Q,K,V row-major (coalesced uint4, no conversion)
    for (int i = tid; i < Tt * 32; i += 256) {
        int r = i >> 5, c8 = (i & 31) * 8;
        *(uint4*)&Qs[r * ASTR + c8] = *(const uint4*)&Q[base + r * 256 + c8];
        *(uint4*)&Ks[r * ASTR + c8] = *(const uint4*)&K[base + r * 256 + c8];
        *(uint4*)&Vc[r * ASTR + c8] = *(const uint4*)&V[base + r * 256 + c8];
    }
    // zero pad rows: Qs 12-15; Ks 12-15, 24-31; Vc 12-15, 24-31 (cols 0..255)
    {
        const uint4 z4 = make_uint4(0u, 0u, 0u, 0u);
        for (int i = tid; i < 28 * 32; i += 256) {
            int rr = i >> 5, c8 = (i & 31) * 8;
            __nv_bfloat16* dst;
            int row;
            if (rr < 4)       { dst = Qs; row = 12 + rr; }
            else if (rr < 8)  { dst = Ks; row = 12 + (rr - 4); }
            else if (rr < 16) { dst = Ks; row = 24 + (rr - 8); }
            else if (rr < 20) { dst = Vc; row = 12 + (rr - 16); }
            else              { dst = Vc; row = 24 + (rr - 20); }
            *(uint4*)&dst[row * ASTR + c8] = z4;
        }
    }
    // mem_k / mem_v into rows 16..23 (warp h, head-local 32 cols; coalesced-ish)
    #pragma unroll
    for (int m = 0; m < Mm; m++) {
        Ks[(16 + m) * ASTR + hc + lane] =
            __float2bfloat16_rn(mem_k[(h * Mm + m) * DK + lane]);
        Vc[(16 + m) * ASTR + hc + lane] =
            __float2bfloat16_rn(mem_v[(h * Mm + m) * DK + lane]);
    }
    // zero P region (16 x 40 halfs = 320 u32)
    {
        uint32_t* pz = (uint32_t*)Ph;
        #pragma unroll
        for (int i = 0; i < 10; i++) pz[lane + i * 32] = 0u;
    }
    __syncthreads();

    const unsigned sQ = (unsigned)__cvta_generic_to_shared(Qs);
    const unsigned sK = (unsigned)__cvta_generic_to_shared(Ks);
    const unsigned sV = (unsigned)__cvta_generic_to_shared(Vc);
    const unsigned sP = (unsigned)__cvta_generic_to_shared(Ph);

    const int arow = lane & 15;
    const int acol = (lane >> 4) << 3;
    const int brow = (lane & 7) + ((lane >> 4) << 3);
    const int bcol = ((lane >> 3) & 1) << 3;
    // trans-LDSM per-lane address components for V
    const int trow = ((lane >> 3) & 1) * 8 + (lane & 7);
    const int tcol = (lane >> 4) << 3;

    // ---- scores: one A-LDSM + two B-LDSM + 3 MMA per kk ----
    float s0[4] = {0.f, 0.f, 0.f, 0.f};
    float s1[4] = {0.f, 0.f, 0.f, 0.f};
    float sm_[4] = {0.f, 0.f, 0.f, 0.f};
    #pragma unroll
    for (int kk = 0; kk < 2; kk++) {
        const int kb = hc + kk * 16;
        unsigned a[4], b01[4], bm[4];
        LDSM_X4(a[0], a[1], a[2], a[3],
                sQ + (unsigned)((arow * ASTR + kb + acol) * 2));
        LDSM_X4(b01[0], b01[1], b01[2], b01[3],
                sK + (unsigned)((brow * ASTR + kb + bcol) * 2));
        LDSM_X4(bm[0], bm[1], bm[2], bm[3],
                sK + (unsigned)(((16 + brow) * ASTR + kb + bcol) * 2));
        mma_bf16(s0, a, &b01[0]);
        mma_bf16(s1, a, &b01[2]);
        mma_bf16(sm_, a, &bm[0]);
    }

    // ---- causal mask + scale ----
    const float scale = 0.1767766952966369f;
    const int s00 = 2 * c, s01 = 2 * c + 1, s10 = 8 + 2 * c, s11 = 8 + 2 * c + 1;
    const int tlo = g, thi = g + 8;
    float e[8];
    e[0] = (s00 <= tlo) ? s0[0] * scale : -1e30f;
    e[1] = (s01 <= tlo) ? s0[1] * scale : -1e30f;
    e[2] = (s10 <= tlo) ? s1[0] * scale : -1e30f;
    e[3] = (s11 <= tlo) ? s1[1] * scale : -1e30f;
    e[4] = (s00 <= thi) ? s0[2] * scale : -1e30f;
    e[5] = (s01 <= thi) ? s0[3] * scale : -1e30f;
    e[6] = (s10 <= thi) ? s1[2] * scale : -1e30f;
    e[7] = (s11 <= thi) ? s1[3] * scale : -1e30f;

    // ---- time softmax (quad shfl) ----
    float mlo = fmaxf(fmaxf(e[0], e[1]), fmaxf(e[2], e[3]));
    float mhi = fmaxf(fmaxf(e[4], e[5]), fmaxf(e[6], e[7]));
    mlo = fmaxf(mlo, __shfl_xor_sync(0xffffffffu, mlo, 1));
    mlo = fmaxf(mlo, __shfl_xor_sync(0xffffffffu, mlo, 2));
    mhi = fmaxf(mhi, __shfl_xor_sync(0xffffffffu, mhi, 1));
    mhi = fmaxf(mhi, __shfl_xor_sync(0xffffffffu, mhi, 2));
    #pragma unroll
    for (int j = 0; j < 4; j++) e[j] = __expf(e[j] - mlo);
    #pragma unroll
    for (int j = 4; j < 8; j++) e[j] = __expf(e[j] - mhi);
    float slo = e[0] + e[1] + e[2] + e[3];
    float shi = e[4] + e[5] + e[6] + e[7];
    slo += __shfl_xor_sync(0xffffffffu, slo, 1);
    slo += __shfl_xor_sync(0xffffffffu, slo, 2);
    shi += __shfl_xor_sync(0xffffffffu, shi, 1);
    shi += __shfl_xor_sync(0xffffffffu, shi, 2);
    float rlo = 1.f / slo, rhi = 1.f / shi;
    #pragma unroll
    for (int j = 0; j < 4; j++) e[j] *= rlo;
    #pragma unroll
    for (int j = 4; j < 8; j++) e[j] *= rhi;

    // ---- memory softmax ----
    float em[4];
    em[0] = sm_[0] * scale; em[1] = sm_[1] * scale;
    em[2] = sm_[2] * scale; em[3] = sm_[3] * scale;
    float mmlo = fmaxf(em[0], em[1]);
    float mmhi = fmaxf(em[2], em[3]);
    mmlo = fmaxf(mmlo, __shfl_xor_sync(0xffffffffu, mmlo, 1));
    mmlo = fmaxf(mmlo, __shfl_xor_sync(0xffffffffu, mmlo, 2));
    mmhi = fmaxf(mmhi, __shfl_xor_sync(0xffffffffu, mmhi, 1));
    mmhi = fmaxf(mmhi, __shfl_xor_sync(0xffffffffu, mmhi, 2));
    em[0] = __expf(em[0] - mmlo); em[1] = __expf(em[1] - mmlo);
    em[2] = __expf(em[2] - mmhi); em[3] = __expf(em[3] - mmhi);
    float smlo = em[0] + em[1];
    float smhi = em[2] + em[3];
    smlo += __shfl_xor_sync(0xffffffffu, smlo, 1);
    smlo += __shfl_xor_sync(0xffffffffu, smlo, 2);
    smhi += __shfl_xor_sync(0xffffffffu, smhi, 1);
    smhi += __shfl_xor_sync(0xffffffffu, smhi, 2);
    em[0] *= 1.f / smlo; em[1] *= 1.f / smlo;
    em[2] *= 1.f / smhi; em[3] *= 1.f / smhi;

    // ---- stage gate-scaled P (bf16): k-cols 0..11 time, 16..23 mem ----
    const float wl = 1.f / (1.f + __expf(-alpha_l[0]));
    const float wt = 1.f - wl;
    Ph[tlo * P_STR + s00] = __float2bfloat16_rn(wt * e[0]);
    Ph[tlo * P_STR + s01] = __float2bfloat16_rn(wt * e[1]);
    Ph[tlo * P_STR + s10] = __float2bfloat16_rn(wt * e[2]);
    Ph[tlo * P_STR + s11] = __float2bfloat16_rn(wt * e[3]);
    Ph[tlo * P_STR + 16 + s00] = __float2bfloat16_rn(wl * em[0]);
    Ph[tlo * P_STR + 16 + s01] = __float2bfloat16_rn(wl * em[1]);
    if (g < 4) {
        Ph[thi * P_STR + s00] = __float2bfloat16_rn(wt * e[4]);
        Ph[thi * P_STR + s01] = __float2bfloat16_rn(wt * e[5]);
        Ph[thi * P_STR + s10] = __float2bfloat16_rn(wt * e[6]);
        Ph[thi * P_STR + s11] = __float2bfloat16_rn(wt * e[7]);
        Ph[thi * P_STR + 16 + s00] = __float2bfloat16_rn(wl * em[2]);
        Ph[thi * P_STR + 16 + s01] = __float2bfloat16_rn(wl * em[3]);
    }
    __syncwarp();

    // ---- O = [P | Pm] . [V ; mem_v]^T : P-LDSM + 2 trans-LDSM + 4 MMA per kk ----
    float o[4][4];
    #pragma unroll
    for (int nt = 0; nt < 4; nt++)
        #pragma unroll
        for (int r = 0; r < 4; r++) o[nt][r] = 0.f;

    #pragma unroll
    for (int kk = 0; kk < 2; kk++) {
        const int kb = kk * 16;
        unsigned pa[4];
        LDSM_X4(pa[0], pa[1], pa[2], pa[3],
                sP + (unsigned)((arow * P_STR + kb + acol) * 2));
        #pragma unroll
        for (int pair = 0; pair < 2; pair++) {
            unsigned vr[4];
            // trans: m0=(kb,d0) m1=(kb+8,d0) m2=(kb,d0+8) m3=(kb+8,d0+8)
            LDSM_X4_T(vr[0], vr[1], vr[2], vr[3],
                      sV + (unsigned)(((kb + trow) * ASTR + hc + pair * 16 + tcol) * 2));
            mma_bf16(o[pair * 2],     pa, &vr[0]);
            mma_bf16(o[pair * 2 + 1], pa, &vr[2]);
        }
    }

    // ---- store (already gated) ----
    #pragma unroll
    for (int nt = 0; nt < 4; nt++) {
        int col = hc + nt * 8 + 2 * c;
        *(__nv_bfloat162*)&out[base + tlo * 256 + col] =
            __float22bfloat162_rn(make_float2(o[nt][0], o[nt][1]));
        if (g < 4) {
            *(__nv_bfloat162*)&out[base + thi * 256 + col] =
                __float22bfloat162_rn(make_float2(o[nt][2], o[nt][3]));
        }
    }
}

// ----------------------------------------------------------------------------
// Launch
// ----------------------------------------------------------------------------
extern "C" void kernel_launch(void* const* d_in, const int* in_sizes, int n_in,
                              void* d_out, int out_size)
{
    const float* x     = (const float*)d_in[0];
    const float* Wq_w  = (const float*)d_in[1];
    const float* Wq_b  = (const float*)d_in[2];
    const float* Wk_w  = (const float*)d_in[3];
    const float* Wk_b  = (const float*)d_in[4];
    const float* Wv_w  = (const float*)d_in[5];
    const float* Wv_b  = (const float*)d_in[6];
    const float* mem_k = (const float*)d_in[7];
    const float* mem_v = (const float*)d_in[8];
    const float* fc_w  = (const float*)d_in[9];
    const float* fc_b  = (const float*)d_in[10];
    const float* gamma = (const float*)d_in[11];
    const float* beta  = (const float*)d_in[12];
    const float* alpha = (const float*)d_in[13];
    float* out = (float*)d_out;

    __nv_bfloat16 *xb, *qb, *kb, *vb, *ab, *wq, *wk, *wv, *wf;
    cudaGetSymbolAddress((void**)&xb, g_xb);
    cudaGetSymbolAddress((void**)&qb, g_qb);
    cudaGetSymbolAddress((void**)&kb, g_kb);
    cudaGetSymbolAddress((void**)&vb, g_vb);
    cudaGetSymbolAddress((void**)&ab, g_ab);
    cudaGetSymbolAddress((void**)&wq, g_wq);
    cudaGetSymbolAddress((void**)&wk, g_wk);
    cudaGetSymbolAddress((void**)&wv, g_wv);
    cudaGetSymbolAddress((void**)&wf, g_wf);

    cudaFuncSetAttribute(attn_kernel,
                         cudaFuncAttributeMaxDynamicSharedMemorySize, ATTN_SMEM);

    const int xn4 = ROWS * Dd / 4;
    cvt_kernel<<<(xn4 + 255) / 256, 256>>>(x, xb, xn4);
    dim3 wgrid(64, 4);
    cvt_w_kernel<<<wgrid, 256>>>(Wq_w, Wk_w, Wv_w, fc_w, wq, wk, wv, wf);

    dim3 qkv_grid(ROWS / 128, 6);
    gemm_qkv_kernel<<<qkv_grid, 256>>>(xb, wq, wk, wv, Wq_b, Wk_b, Wv_b, qb, kb, vb);

    attn_kernel<<<BN_CNT, 256, ATTN_SMEM>>>(qb, kb, vb, mem_k, mem_v, alpha, ab);

    gemm_fc_ln_kernel<<<ROWS / 128, 256>>>(ab, wf, fc_b, x, gamma, beta, out);
}

// round 13
// speedup vs baseline: 1.2790x; 1.0513x over previous
#include <cuda_runtime.h>
#include <cuda_bf16.h>
#include <math.h>
#include <stdint.h>

#define Bb 8
#define Nn 2048
#define Tt 12
#define Dd 256
#define Hh 8
#define DK 32
#define Mm 8
#define ROWS (Bb * Nn * Tt)          // 196608
#define BN_CNT (Bb * Nn)             // 16384

// Scratch (device globals; allocation-free rule)
__device__ __nv_bfloat16 g_xb[ROWS * Dd];
__device__ __nv_bfloat16 g_qb[ROWS * Dd];
__device__ __nv_bfloat16 g_kb[ROWS * Dd];
__device__ __nv_bfloat16 g_vb[ROWS * Dd];
__device__ __nv_bfloat16 g_ab[ROWS * Dd];
__device__ __nv_bfloat16 g_wq[Dd * Dd];
__device__ __nv_bfloat16 g_wk[Dd * Dd];
__device__ __nv_bfloat16 g_wv[Dd * Dd];
__device__ __nv_bfloat16 g_wf[Dd * Dd];

#define CP_ASYNC16(dst, src) \
    asm volatile("cp.async.cg.shared.global [%0], [%1], 16;" :: "r"(dst), "l"(src))
#define CP_COMMIT() asm volatile("cp.async.commit_group;")
#define CP_WAIT(n)  asm volatile("cp.async.wait_group %0;" :: "n"(n))

#define LDSM_X4(r0, r1, r2, r3, addr) \
    asm volatile("ldmatrix.sync.aligned.m8n8.x4.shared.b16 {%0,%1,%2,%3}, [%4];" \
        : "=r"(r0), "=r"(r1), "=r"(r2), "=r"(r3) : "r"(addr))

#define LDSM_X4_T(r0, r1, r2, r3, addr) \
    asm volatile("ldmatrix.sync.aligned.m8n8.x4.trans.shared.b16 {%0,%1,%2,%3}, [%4];" \
        : "=r"(r0), "=r"(r1), "=r"(r2), "=r"(r3) : "r"(addr))

__device__ __forceinline__ void mma_bf16(float* c, const unsigned* a, const unsigned* b) {
    asm volatile(
        "mma.sync.aligned.m16n8k16.row.col.f32.bf16.bf16.f32 "
        "{%0,%1,%2,%3}, {%4,%5,%6,%7}, {%8,%9}, {%0,%1,%2,%3};"
        : "+f"(c[0]), "+f"(c[1]), "+f"(c[2]), "+f"(c[3])
        : "r"(a[0]), "r"(a[1]), "r"(a[2]), "r"(a[3]), "r"(b[0]), "r"(b[1]));
}

// ----------------------------------------------------------------------------
// fp32 -> bf16 conversions
// ----------------------------------------------------------------------------
__global__ __launch_bounds__(256) void cvt_kernel(
    const float* __restrict__ in, __nv_bfloat16* __restrict__ out, int n4)
{
    int i = blockIdx.x * 256 + threadIdx.x;
    if (i < n4) {
        float4 v = ((const float4*)in)[i];
        ((__nv_bfloat162*)out)[2 * i]     = __float22bfloat162_rn(make_float2(v.x, v.y));
        ((__nv_bfloat162*)out)[2 * i + 1] = __float22bfloat162_rn(make_float2(v.z, v.w));
    }
}

__global__ __launch_bounds__(256) void cvt_w_kernel(
    const float* __restrict__ w0, const float* __restrict__ w1,
    const float* __restrict__ w2, const float* __restrict__ w3,
    __nv_bfloat16* __restrict__ d0, __nv_bfloat16* __restrict__ d1,
    __nv_bfloat16* __restrict__ d2, __nv_bfloat16* __restrict__ d3)
{
    const int sel = blockIdx.y;
    const float* in = (sel == 0) ? w0 : (sel == 1) ? w1 : (sel == 2) ? w2 : w3;
    __nv_bfloat16* out = (sel == 0) ? d0 : (sel == 1) ? d1 : (sel == 2) ? d2 : d3;
    int i = blockIdx.x * 256 + threadIdx.x;
    float4 v = ((const float4*)in)[i];
    ((__nv_bfloat162*)out)[2 * i]     = __float22bfloat162_rn(make_float2(v.x, v.y));
    ((__nv_bfloat162*)out)[2 * i + 1] = __float22bfloat162_rn(make_float2(v.z, v.w));
}

// ----------------------------------------------------------------------------
// QKV GEMM v3: BM=BN=128, BK=32, 3-stage cp.async, SINGLE sync per k-iter.
// grid = (6, ROWS/128): consecutive CTA ids share one A tile -> A hits L2.
// Dynamic smem: As[3][128][40] + Bs[3][128][40] = 61440 B.
// ----------------------------------------------------------------------------
#define QKV_STG (128 * 40 * 2)          // bytes per stage (one matrix)
#define QKV_SMEM (6 * QKV_STG)          // 61440

__global__ __launch_bounds__(256) void gemm_qkv_kernel(
    const __nv_bfloat16* __restrict__ xb,
    const __nv_bfloat16* __restrict__ wq, const __nv_bfloat16* __restrict__ wk,
    const __nv_bfloat16* __restrict__ wv,
    const float* __restrict__ bq, const float* __restrict__ bk,
    const float* __restrict__ bv,
    __nv_bfloat16* __restrict__ qb, __nv_bfloat16* __restrict__ kb,
    __nv_bfloat16* __restrict__ vb)
{
    extern __shared__ __nv_bfloat16 qsm[];

    const int sel = blockIdx.x >> 1;          // 0,1,2 -> q,k,v
    const int n0  = (blockIdx.x & 1) * 128;
    const int m0  = blockIdx.y * 128;
    const __nv_bfloat16* A = xb;
    const __nv_bfloat16* W = (sel == 0) ? wq : (sel == 1) ? wk : wv;
    const float* bias      = (sel == 0) ? bq : (sel == 1) ? bk : bv;
    __nv_bfloat16* C       = (sel == 0) ? qb : (sel == 1) ? kb : vb;

    const int tid  = threadIdx.x;
    const int lane = tid & 31;
    const int wid  = tid >> 5;
    const int wm   = (wid >> 2) * 64;
    const int wn   = (wid & 3) * 32;
    const int g    = lane >> 2;
    const int c    = lane & 3;

    float acc[4][4][4];
    #pragma unroll
    for (int i = 0; i < 4; i++)
        #pragma unroll
        for (int j = 0; j < 4; j++)
            #pragma unroll
            for (int r = 0; r < 4; r++) acc[i][j][r] = 0.f;

    const int idx0 = tid * 2;
    const int r0   = idx0 >> 2;
    const int h0   = (idx0 & 3) << 3;
    const int idx1 = idx0 + 1;
    const int r1   = idx1 >> 2;
    const int h1   = (idx1 & 3) << 3;

    const unsigned sA = (unsigned)__cvta_generic_to_shared(qsm);
    const unsigned sB = sA + 3 * QKV_STG;

    auto load_tile = [&](int st, int k0) {
        CP_ASYNC16(sA + st * QKV_STG + (r0 * 40 + h0) * 2, &A[(size_t)(m0 + r0) * 256 + k0 + h0]);
        CP_ASYNC16(sB + st * QKV_STG + (r0 * 40 + h0) * 2, &W[(size_t)(n0 + r0) * 256 + k0 + h0]);
        CP_ASYNC16(sA + st * QKV_STG + (r1 * 40 + h1) * 2, &A[(size_t)(m0 + r1) * 256 + k0 + h1]);
        CP_ASYNC16(sB + st * QKV_STG + (r1 * 40 + h1) * 2, &W[(size_t)(n0 + r1) * 256 + k0 + h1]);
    };

    const int arow = lane & 15;
    const int acol = (lane >> 4) << 3;
    const int brow = (lane & 7) + ((lane >> 4) << 3);
    const int bcol = ((lane >> 3) & 1) << 3;

    load_tile(0, 0);  CP_COMMIT();
    load_tile(1, 32); CP_COMMIT();

    #pragma unroll
    for (int kt = 0; kt < 8; kt++) {
        const int st = kt % 3;
        if (kt == 7) { CP_WAIT(0); } else { CP_WAIT(1); }
        __syncthreads();
        // load into stage (kt+2)%3 == (kt-1)%3: consumed at iter kt-1, all warps
        // past that compute (the sync above). Single barrier per iter.
        if (kt + 2 < 8) { load_tile((kt + 2) % 3, (kt + 2) * 32); CP_COMMIT(); }

        #pragma unroll
        for (int kk = 0; kk < 2; kk++) {
            const int kb = kk * 16;
            unsigned af[4][4];
            unsigned bf[4][2];
            #pragma unroll
            for (int im = 0; im < 4; im++) {
                unsigned addr = sA + st * QKV_STG +
                    (unsigned)(((wm + im * 16 + arow) * 40 + kb + acol) * 2);
                LDSM_X4(af[im][0], af[im][1], af[im][2], af[im][3], addr);
            }
            #pragma unroll
            for (int np = 0; np < 2; np++) {
                unsigned addr = sB + st * QKV_STG +
                    (unsigned)(((wn + np * 16 + brow) * 40 + kb + bcol) * 2);
                LDSM_X4(bf[2 * np][0], bf[2 * np][1], bf[2 * np + 1][0], bf[2 * np + 1][1], addr);
            }
            #pragma unroll
            for (int im = 0; im < 4; im++)
                #pragma unroll
                for (int in_ = 0; in_ < 4; in_++)
                    mma_bf16(acc[im][in_], af[im], bf[in_]);
        }
    }

    #pragma unroll
    for (int im = 0; im < 4; im++) {
        int row = m0 + wm + im * 16 + g;
        #pragma unroll
        for (int in_ = 0; in_ < 4; in_++) {
            int col = n0 + wn + in_ * 8 + 2 * c;
            float b0 = bias[col], b1 = bias[col + 1];
            *(__nv_bfloat162*)&C[(size_t)row * 256 + col] =
                __float22bfloat162_rn(make_float2(acc[im][in_][0] + b0, acc[im][in_][1] + b1));
            *(__nv_bfloat162*)&C[(size_t)(row + 8) * 256 + col] =
                __float22bfloat162_rn(make_float2(acc[im][in_][2] + b0, acc[im][in_][3] + b1));
        }
    }
}

// ----------------------------------------------------------------------------
// Fused FC GEMM + residual + LayerNorm (R8, proven).
// ----------------------------------------------------------------------------
#define FSTR 24

__global__ __launch_bounds__(256) void gemm_fc_ln_kernel(
    const __nv_bfloat16* __restrict__ A, const __nv_bfloat16* __restrict__ W,
    const float* __restrict__ bias, const float* __restrict__ x,
    const float* __restrict__ gamma, const float* __restrict__ beta,
    float* __restrict__ out)
{
    __shared__ __nv_bfloat16 As[2][128][FSTR];
    __shared__ __nv_bfloat16 Bs[2][256][FSTR];
    __shared__ float psum[8][64];
    __shared__ float psum2[8][64];
    __shared__ float smu[128];
    __shared__ float srstd[128];

    const int tid  = threadIdx.x;
    const int lane = tid & 31;
    const int wid  = tid >> 5;
    const int wm   = (wid >> 2) * 64;
    const int wn   = (wid & 3) * 64;
    const int m0   = blockIdx.x * 128;
    const int g    = lane >> 2;
    const int c    = lane & 3;

    float acc[4][8][4];
    #pragma unroll
    for (int i = 0; i < 4; i++)
        #pragma unroll
        for (int j = 0; j < 8; j++)
            #pragma unroll
            for (int r = 0; r < 4; r++) acc[i][j][r] = 0.f;

    const int rA = tid >> 1;
    const int cC = (tid & 1) << 3;

    const unsigned sA = (unsigned)__cvta_generic_to_shared(&As[0][0][0]);
    const unsigned sB = (unsigned)__cvta_generic_to_shared(&Bs[0][0][0]);
    const unsigned ASTG = 128 * FSTR * 2;
    const unsigned BSTG = 256 * FSTR * 2;

    auto load_tile = [&](int st, int k0) {
        CP_ASYNC16(sA + st * ASTG + (rA * FSTR + cC) * 2,
                   &A[(size_t)(m0 + rA) * 256 + k0 + cC]);
        CP_ASYNC16(sB + st * BSTG + (rA * FSTR + cC) * 2,
                   &W[(size_t)rA * 256 + k0 + cC]);
        CP_ASYNC16(sB + st * BSTG + ((128 + rA) * FSTR + cC) * 2,
                   &W[(size_t)(128 + rA) * 256 + k0 + cC]);
    };

    const int arow = lane & 15;
    const int acol = (lane >> 4) << 3;
    const int brow = (lane & 7) + ((lane >> 4) << 3);
    const int bcol = ((lane >> 3) & 1) << 3;

    load_tile(0, 0);  CP_COMMIT();
    load_tile(1, 16); CP_COMMIT();

    #pragma unroll
    for (int kt = 0; kt < 16; kt++) {
        const int st = kt & 1;
        if (kt == 15) { CP_WAIT(0); } else { CP_WAIT(1); }
        __syncthreads();

        unsigned af[4][4];
        unsigned bf[8][2];
        #pragma unroll
        for (int im = 0; im < 4; im++) {
            unsigned addr = sA + st * ASTG +
                (unsigned)(((wm + im * 16 + arow) * FSTR + acol) * 2);
            LDSM_X4(af[im][0], af[im][1], af[im][2], af[im][3], addr);
        }
        #pragma unroll
        for (int np = 0; np < 4; np++) {
            unsigned addr = sB + st * BSTG +
                (unsigned)(((wn + np * 16 + brow) * FSTR + bcol) * 2);
            LDSM_X4(bf[2 * np][0], bf[2 * np][1], bf[2 * np + 1][0], bf[2 * np + 1][1], addr);
        }
        #pragma unroll
        for (int im = 0; im < 4; im++)
            #pragma unroll
            for (int in_ = 0; in_ < 8; in_++)
                mma_bf16(acc[im][in_], af[im], bf[in_]);

        __syncthreads();
        if (kt + 2 < 16) { load_tile(st, (kt + 2) * 16); CP_COMMIT(); }
    }

    #pragma unroll
    for (int im = 0; im < 4; im++) {
        size_t row  = (size_t)(m0 + wm + im * 16 + g) * 256;
        size_t row2 = row + 8 * 256;
        float s1 = 0.f, q1 = 0.f, s2 = 0.f, q2 = 0.f;
        #pragma unroll
        for (int in_ = 0; in_ < 8; in_++) {
            int col = wn + in_ * 8 + 2 * c;
            float b0 = bias[col], b1 = bias[col + 1];
            float2 x0 = *(const float2*)&x[row + col];
            float2 x1 = *(const float2*)&x[row2 + col];
            float v00 = acc[im][in_][0] + b0 + x0.x;
            float v01 = acc[im][in_][1] + b1 + x0.y;
            float v10 = acc[im][in_][2] + b0 + x1.x;
            float v11 = acc[im][in_][3] + b1 + x1.y;
            acc[im][in_][0] = v00; acc[im][in_][1] = v01;
            acc[im][in_][2] = v10; acc[im][in_][3] = v11;
            s1 += v00 + v01; q1 += v00 * v00 + v01 * v01;
            s2 += v10 + v11; q2 += v10 * v10 + v11 * v11;
        }
        #pragma unroll
        for (int off = 1; off <= 2; off <<= 1) {
            s1 += __shfl_xor_sync(0xffffffffu, s1, off);
            q1 += __shfl_xor_sync(0xffffffffu, q1, off);
            s2 += __shfl_xor_sync(0xffffffffu, s2, off);
            q2 += __shfl_xor_sync(0xffffffffu, q2, off);
        }
        if (c == 0) {
            psum[wid][im * 16 + g]      = s1;
            psum2[wid][im * 16 + g]     = q1;
            psum[wid][im * 16 + g + 8]  = s2;
            psum2[wid][im * 16 + g + 8] = q2;
        }
    }
    __syncthreads();

    if (tid < 128) {
        const int half = tid >> 6;
        const int ri   = tid & 63;
        float s = 0.f, q = 0.f;
        #pragma unroll
        for (int j = 0; j < 4; j++) {
            s += psum[half * 4 + j][ri];
            q += psum2[half * 4 + j][ri];
        }
        float mu  = s * (1.f / 256.f);
        float var = q * (1.f / 256.f) - mu * mu;
        smu[tid]   = mu;
        srstd[tid] = rsqrtf(var + 1e-5f);
    }
    __syncthreads();

    #pragma unroll
    for (int im = 0; im < 4; im++) {
        int rl = wm + im * 16 + g;
        float mu1 = smu[rl],     rs1 = srstd[rl];
        float mu2 = smu[rl + 8], rs2 = srstd[rl + 8];
        size_t row  = (size_t)(m0 + rl) * 256;
        size_t row2 = row + 8 * 256;
        #pragma unroll
        for (int in_ = 0; in_ < 8; in_++) {
            int col = wn + in_ * 8 + 2 * c;
            float ga0 = gamma[col], ga1 = gamma[col + 1];
            float be0 = beta[col],  be1 = beta[col + 1];
            *(float2*)&out[row + col] = make_float2(
                (acc[im][in_][0] - mu1) * rs1 * ga0 + be0,
                (acc[im][in_][1] - mu1) * rs1 * ga1 + be1);
            *(float2*)&out[row2 + col] = make_float2(
                (acc[im][in_][2] - mu2) * rs2 * ga0 + be0,
                (acc[im][in_][3] - mu2) * rs2 * ga1 + be1);
        }
    }
}

// ----------------------------------------------------------------------------
// Attention v6 (R12, proven): all-bf16, all fragments via ldmatrix (trans for V).
// ----------------------------------------------------------------------------
#define ASTR 264
#define P_STR 40
#define ATTN_SMEM ((80 * ASTR + Hh * 16 * P_STR) * 2)   // 52480 bytes

__global__ __launch_bounds__(256) void attn_kernel(
    const __nv_bfloat16* __restrict__ Q, const __nv_bfloat16* __restrict__ K,
    const __nv_bfloat16* __restrict__ V,
    const float* __restrict__ mem_k, const float* __restrict__ mem_v,
    const float* __restrict__ alpha_l, __nv_bfloat16* __restrict__ out)
{
    extern __shared__ __nv_bfloat16 smem_attn[];
    __nv_bfloat16* Qs = smem_attn;              // 16 rows
    __nv_bfloat16* Ks = smem_attn + 16 * ASTR;  // 32 rows
    __nv_bfloat16* Vc = smem_attn + 48 * ASTR;  // 32 rows

    const int tid  = threadIdx.x;
    const int lane = tid & 31;
    const int h    = tid >> 5;
    const int g    = lane >> 2;
    const int c    = lane & 3;
    const int hc   = h * DK;
    const size_t base = (size_t)blockIdx.x * (Tt * Dd);

    __nv_bfloat16* Ph = smem_attn + 80 * ASTR + h * (16 * P_STR);

    for (int i = tid; i < Tt * 32; i += 256) {
        int r = i >> 5, c8 = (i & 31) * 8;
        *(uint4*)&Qs[r * ASTR + c8] = *(const uint4*)&Q[base + r * 256 + c8];
        *(uint4*)&Ks[r * ASTR + c8] = *(const uint4*)&K[base + r * 256 + c8];
        *(uint4*)&Vc[r * ASTR + c8] = *(const uint4*)&V[base + r * 256 + c8];
    }
    {
        const uint4 z4 = make_uint4(0u, 0u, 0u, 0u);
        for (int i = tid; i < 28 * 32; i += 256) {
            int rr = i >> 5, c8 = (i & 31) * 8;
            __nv_bfloat16* dst;
            int row;
            if (rr < 4)       { dst = Qs; row = 12 + rr; }
            else if (rr < 8)  { dst = Ks; row = 12 + (rr - 4); }
            else if (rr < 16) { dst = Ks; row = 24 + (rr - 8); }
            else if (rr < 20) { dst = Vc; row = 12 + (rr - 16); }
            else              { dst = Vc; row = 24 + (rr - 20); }
            *(uint4*)&dst[row * ASTR + c8] = z4;
        }
    }
    #pragma unroll
    for (int m = 0; m < Mm; m++) {
        Ks[(16 + m) * ASTR + hc + lane] =
            __float2bfloat16_rn(mem_k[(h * Mm + m) * DK + lane]);
        Vc[(16 + m) * ASTR + hc + lane] =
            __float2bfloat16_rn(mem_v[(h * Mm + m) * DK + lane]);
    }
    {
        uint32_t* pz = (uint32_t*)Ph;
        #pragma unroll
        for (int i = 0; i < 10; i++) pz[lane + i * 32] = 0u;
    }
    __syncthreads();

    const unsigned sQ = (unsigned)__cvta_generic_to_shared(Qs);
    const unsigned sK = (unsigned)__cvta_generic_to_shared(Ks);
    const unsigned sV = (unsigned)__cvta_generic_to_shared(Vc);
    const unsigned sP = (unsigned)__cvta_generic_to_shared(Ph);

    const int arow = lane & 15;
    const int acol = (lane >> 4) << 3;
    const int brow = (lane & 7) + ((lane >> 4) << 3);
    const int bcol = ((lane >> 3) & 1) << 3;
    const int trow = ((lane >> 3) & 1) * 8 + (lane & 7);
    const int tcol = (lane >> 4) << 3;

    float s0[4] = {0.f, 0.f, 0.f, 0.f};
    float s1[4] = {0.f, 0.f, 0.f, 0.f};
    float sm_[4] = {0.f, 0.f, 0.f, 0.f};
    #pragma unroll
    for (int kk = 0; kk < 2; kk++) {
        const int kb = hc + kk * 16;
        unsigned a[4], b01[4], bm[4];
        LDSM_X4(a[0], a[1], a[2], a[3],
                sQ + (unsigned)((arow * ASTR + kb + acol) * 2));
        LDSM_X4(b01[0], b01[1], b01[2], b01[3],
                sK + (unsigned)((brow * ASTR + kb + bcol) * 2));
        LDSM_X4(bm[0], bm[1], bm[2], bm[3],
                sK + (unsigned)(((16 + brow) * ASTR + kb + bcol) * 2));
        mma_bf16(s0, a, &b01[0]);
        mma_bf16(s1, a, &b01[2]);
        mma_bf16(sm_, a, &bm[0]);
    }

    const float scale = 0.1767766952966369f;
    const int s00 = 2 * c, s01 = 2 * c + 1, s10 = 8 + 2 * c, s11 = 8 + 2 * c + 1;
    const int tlo = g, thi = g + 8;
    float e[8];
    e[0] = (s00 <= tlo) ? s0[0] * scale : -1e30f;
    e[1] = (s01 <= tlo) ? s0[1] * scale : -1e30f;
    e[2] = (s10 <= tlo) ? s1[0] * scale : -1e30f;
    e[3] = (s11 <= tlo) ? s1[1] * scale : -1e30f;
    e[4] = (s00 <= thi) ? s0[2] * scale : -1e30f;
    e[5] = (s01 <= thi) ? s0[3] * scale : -1e30f;
    e[6] = (s10 <= thi) ? s1[2] * scale : -1e30f;
    e[7] = (s11 <= thi) ? s1[3] * scale : -1e30f;

    float mlo = fmaxf(fmaxf(e[0], e[1]), fmaxf(e[2], e[3]));
    float mhi = fmaxf(fmaxf(e[4], e[5]), fmaxf(e[6], e[7]));
    mlo = fmaxf(mlo, __shfl_xor_sync(0xffffffffu, mlo, 1));
    mlo = fmaxf(mlo, __shfl_xor_sync(0xffffffffu, mlo, 2));
    mhi = fmaxf(mhi, __shfl_xor_sync(0xffffffffu, mhi, 1));
    mhi = fmaxf(mhi, __shfl_xor_sync(0xffffffffu, mhi, 2));
    #pragma unroll
    for (int j = 0; j < 4; j++) e[j] = __expf(e[j] - mlo);
    #pragma unroll
    for (int j = 4; j < 8; j++) e[j] = __expf(e[j] - mhi);
    float slo = e[0] + e[1] + e[2] + e[3];
    float shi = e[4] + e[5] + e[6] + e[7];
    slo += __shfl_xor_sync(0xffffffffu, slo, 1);
    slo += __shfl_xor_sync(0xffffffffu, slo, 2);
    shi += __shfl_xor_sync(0xffffffffu, shi, 1);
    shi += __shfl_xor_sync(0xffffffffu, shi, 2);
    float rlo = 1.f / slo, rhi = 1.f / shi;
    #pragma unroll
    for (int j = 0; j < 4; j++) e[j] *= rlo;
    #pragma unroll
    for (int j = 4; j < 8; j++) e[j] *= rhi;

    float em[4];
    em[0] = sm_[0] * scale; em[1] = sm_[1] * scale;
    em[2] = sm_[2] * scale; em[3] = sm_[3] * scale;
    float mmlo = fmaxf(em[0], em[1]);
    float mmhi = fmaxf(em[2], em[3]);
    mmlo = fmaxf(mmlo, __shfl_xor_sync(0xffffffffu, mmlo, 1));
    mmlo = fmaxf(mmlo, __shfl_xor_sync(0xffffffffu, mmlo, 2));
    mmhi = fmaxf(mmhi, __shfl_xor_sync(0xffffffffu, mmhi, 1));
    mmhi = fmaxf(mmhi, __shfl_xor_sync(0xffffffffu, mmhi, 2));
    em[0] = __expf(em[0] - mmlo); em[1] = __expf(em[1] - mmlo);
    em[2] = __expf(em[2] - mmhi); em[3] = __expf(em[3] - mmhi);
    float smlo = em[0] + em[1];
    float smhi = em[2] + em[3];
    smlo += __shfl_xor_sync(0xffffffffu, smlo, 1);
    smlo += __shfl_xor_sync(0xffffffffu, smlo, 2);
    smhi += __shfl_xor_sync(0xffffffffu, smhi, 1);
    smhi += __shfl_xor_sync(0xffffffffu, smhi, 2);
    em[0] *= 1.f / smlo; em[1] *= 1.f / smlo;
    em[2] *= 1.f / smhi; em[3] *= 1.f / smhi;

    const float wl = 1.f / (1.f + __expf(-alpha_l[0]));
    const float wt = 1.f - wl;
    Ph[tlo * P_STR + s00] = __float2bfloat16_rn(wt * e[0]);
    Ph[tlo * P_STR + s01] = __float2bfloat16_rn(wt * e[1]);
    Ph[tlo * P_STR + s10] = __float2bfloat16_rn(wt * e[2]);
    Ph[tlo * P_STR + s11] = __float2bfloat16_rn(wt * e[3]);
    Ph[tlo * P_STR + 16 + s00] = __float2bfloat16_rn(wl * em[0]);
    Ph[tlo * P_STR + 16 + s01] = __float2bfloat16_rn(wl * em[1]);
    if (g < 4) {
        Ph[thi * P_STR + s00] = __float2bfloat16_rn(wt * e[4]);
        Ph[thi * P_STR + s01] = __float2bfloat16_rn(wt * e[5]);
        Ph[thi * P_STR + s10] = __float2bfloat16_rn(wt * e[6]);
        Ph[thi * P_STR + s11] = __float2bfloat16_rn(wt * e[7]);
        Ph[thi * P_STR + 16 + s00] = __float2bfloat16_rn(wl * em[2]);
        Ph[thi * P_STR + 16 + s01] = __float2bfloat16_rn(wl * em[3]);
    }
    __syncwarp();

    float o[4][4];
    #pragma unroll
    for (int nt = 0; nt < 4; nt++)
        #pragma unroll
        for (int r = 0; r < 4; r++) o[nt][r] = 0.f;

    #pragma unroll
    for (int kk = 0; kk < 2; kk++) {
        const int kb = kk * 16;
        unsigned pa[4];
        LDSM_X4(pa[0], pa[1], pa[2], pa[3],
                sP + (unsigned)((arow * P_STR + kb + acol) * 2));
        #pragma unroll
        for (int pair = 0; pair < 2; pair++) {
            unsigned vr[4];
            LDSM_X4_T(vr[0], vr[1], vr[2], vr[3],
                      sV + (unsigned)(((kb + trow) * ASTR + hc + pair * 16 + tcol) * 2));
            mma_bf16(o[pair * 2],     pa, &vr[0]);
            mma_bf16(o[pair * 2 + 1], pa, &vr[2]);
        }
    }

    #pragma unroll
    for (int nt = 0; nt < 4; nt++) {
        int col = hc + nt * 8 + 2 * c;
        *(__nv_bfloat162*)&out[base + tlo * 256 + col] =
            __float22bfloat162_rn(make_float2(o[nt][0], o[nt][1]));
        if (g < 4) {
            *(__nv_bfloat162*)&out[base + thi * 256 + col] =
                __float22bfloat162_rn(make_float2(o[nt][2], o[nt][3]));
        }
    }
}

// ----------------------------------------------------------------------------
// Launch
// ----------------------------------------------------------------------------
extern "C" void kernel_launch(void* const* d_in, const int* in_sizes, int n_in,
                              void* d_out, int out_size)
{
    const float* x     = (const float*)d_in[0];
    const float* Wq_w  = (const float*)d_in[1];
    const float* Wq_b  = (const float*)d_in[2];
    const float* Wk_w  = (const float*)d_in[3];
    const float* Wk_b  = (const float*)d_in[4];
    const float* Wv_w  = (const float*)d_in[5];
    const float* Wv_b  = (const float*)d_in[6];
    const float* mem_k = (const float*)d_in[7];
    const float* mem_v = (const float*)d_in[8];
    const float* fc_w  = (const float*)d_in[9];
    const float* fc_b  = (const float*)d_in[10];
    const float* gamma = (const float*)d_in[11];
    const float* beta  = (const float*)d_in[12];
    const float* alpha = (const float*)d_in[13];
    float* out = (float*)d_out;

    __nv_bfloat16 *xb, *qb, *kb, *vb, *ab, *wq, *wk, *wv, *wf;
    cudaGetSymbolAddress((void**)&xb, g_xb);
    cudaGetSymbolAddress((void**)&qb, g_qb);
    cudaGetSymbolAddress((void**)&kb, g_kb);
    cudaGetSymbolAddress((void**)&vb, g_vb);
    cudaGetSymbolAddress((void**)&ab, g_ab);
    cudaGetSymbolAddress((void**)&wq, g_wq);
    cudaGetSymbolAddress((void**)&wk, g_wk);
    cudaGetSymbolAddress((void**)&wv, g_wv);
    cudaGetSymbolAddress((void**)&wf, g_wf);

    cudaFuncSetAttribute(attn_kernel,
                         cudaFuncAttributeMaxDynamicSharedMemorySize, ATTN_SMEM);
    cudaFuncSetAttribute(gemm_qkv_kernel,
                         cudaFuncAttributeMaxDynamicSharedMemorySize, QKV_SMEM);

    const int xn4 = ROWS * Dd / 4;
    cvt_kernel<<<(xn4 + 255) / 256, 256>>>(x, xb, xn4);
    dim3 wgrid(64, 4);
    cvt_w_kernel<<<wgrid, 256>>>(Wq_w, Wk_w, Wv_w, fc_w, wq, wk, wv, wf);

    dim3 qkv_grid(6, ROWS / 128);
    gemm_qkv_kernel<<<qkv_grid, 256, QKV_SMEM>>>(
        xb, wq, wk, wv, Wq_b, Wk_b, Wv_b, qb, kb, vb);

    attn_kernel<<<BN_CNT, 256, ATTN_SMEM>>>(qb, kb, vb, mem_k, mem_v, alpha, ab);

    gemm_fc_ln_kernel<<<ROWS / 128, 256>>>(ab, wf, fc_b, x, gamma, beta, out);
}

// round 14
// speedup vs baseline: 1.3154x; 1.0284x over previous
#include <cuda_runtime.h>
#include <cuda_bf16.h>
#include <math.h>
#include <stdint.h>

#define Bb 8
#define Nn 2048
#define Tt 12
#define Dd 256
#define Hh 8
#define DK 32
#define Mm 8
#define ROWS (Bb * Nn * Tt)          // 196608
#define BN_CNT (Bb * Nn)             // 16384

// Scratch (device globals; allocation-free rule)
__device__ __nv_bfloat16 g_xb[ROWS * Dd];
__device__ __nv_bfloat16 g_qb[ROWS * Dd];
__device__ __nv_bfloat16 g_kb[ROWS * Dd];
__device__ __nv_bfloat16 g_vb[ROWS * Dd];
__device__ __nv_bfloat16 g_ab[ROWS * Dd];
__device__ __nv_bfloat16 g_wq[Dd * Dd];
__device__ __nv_bfloat16 g_wk[Dd * Dd];
__device__ __nv_bfloat16 g_wv[Dd * Dd];
__device__ __nv_bfloat16 g_wf[Dd * Dd];

#define CP_ASYNC16(dst, src) \
    asm volatile("cp.async.cg.shared.global [%0], [%1], 16;" :: "r"(dst), "l"(src))
#define CP_COMMIT() asm volatile("cp.async.commit_group;")
#define CP_WAIT(n)  asm volatile("cp.async.wait_group %0;" :: "n"(n))

#define LDSM_X4(r0, r1, r2, r3, addr) \
    asm volatile("ldmatrix.sync.aligned.m8n8.x4.shared.b16 {%0,%1,%2,%3}, [%4];" \
        : "=r"(r0), "=r"(r1), "=r"(r2), "=r"(r3) : "r"(addr))

#define LDSM_X4_T(r0, r1, r2, r3, addr) \
    asm volatile("ldmatrix.sync.aligned.m8n8.x4.trans.shared.b16 {%0,%1,%2,%3}, [%4];" \
        : "=r"(r0), "=r"(r1), "=r"(r2), "=r"(r3) : "r"(addr))

__device__ __forceinline__ void mma_bf16(float* c, const unsigned* a, const unsigned* b) {
    asm volatile(
        "mma.sync.aligned.m16n8k16.row.col.f32.bf16.bf16.f32 "
        "{%0,%1,%2,%3}, {%4,%5,%6,%7}, {%8,%9}, {%0,%1,%2,%3};"
        : "+f"(c[0]), "+f"(c[1]), "+f"(c[2]), "+f"(c[3])
        : "r"(a[0]), "r"(a[1]), "r"(a[2]), "r"(a[3]), "r"(b[0]), "r"(b[1]));
}

// ----------------------------------------------------------------------------
// fp32 -> bf16 conversions
// ----------------------------------------------------------------------------
__global__ __launch_bounds__(256) void cvt_kernel(
    const float* __restrict__ in, __nv_bfloat16* __restrict__ out, int n4)
{
    int i = blockIdx.x * 256 + threadIdx.x;
    if (i < n4) {
        float4 v = ((const float4*)in)[i];
        ((__nv_bfloat162*)out)[2 * i]     = __float22bfloat162_rn(make_float2(v.x, v.y));
        ((__nv_bfloat162*)out)[2 * i + 1] = __float22bfloat162_rn(make_float2(v.z, v.w));
    }
}

__global__ __launch_bounds__(256) void cvt_w_kernel(
    const float* __restrict__ w0, const float* __restrict__ w1,
    const float* __restrict__ w2, const float* __restrict__ w3,
    __nv_bfloat16* __restrict__ d0, __nv_bfloat16* __restrict__ d1,
    __nv_bfloat16* __restrict__ d2, __nv_bfloat16* __restrict__ d3)
{
    const int sel = blockIdx.y;
    const float* in = (sel == 0) ? w0 : (sel == 1) ? w1 : (sel == 2) ? w2 : w3;
    __nv_bfloat16* out = (sel == 0) ? d0 : (sel == 1) ? d1 : (sel == 2) ? d2 : d3;
    int i = blockIdx.x * 256 + threadIdx.x;
    float4 v = ((const float4*)in)[i];
    ((__nv_bfloat162*)out)[2 * i]     = __float22bfloat162_rn(make_float2(v.x, v.y));
    ((__nv_bfloat162*)out)[2 * i + 1] = __float22bfloat162_rn(make_float2(v.z, v.w));
}

// ----------------------------------------------------------------------------
// QKV GEMM v3 (R13, proven): BM=BN=128, BK=32, 3-stage cp.async, single sync.
// grid = (6, ROWS/128): consecutive CTA ids share one A tile -> A hits L2.
// ----------------------------------------------------------------------------
#define QKV_STG (128 * 40 * 2)
#define QKV_SMEM (6 * QKV_STG)          // 61440

__global__ __launch_bounds__(256) void gemm_qkv_kernel(
    const __nv_bfloat16* __restrict__ xb,
    const __nv_bfloat16* __restrict__ wq, const __nv_bfloat16* __restrict__ wk,
    const __nv_bfloat16* __restrict__ wv,
    const float* __restrict__ bq, const float* __restrict__ bk,
    const float* __restrict__ bv,
    __nv_bfloat16* __restrict__ qb, __nv_bfloat16* __restrict__ kb,
    __nv_bfloat16* __restrict__ vb)
{
    extern __shared__ __nv_bfloat16 qsm[];

    const int sel = blockIdx.x >> 1;
    const int n0  = (blockIdx.x & 1) * 128;
    const int m0  = blockIdx.y * 128;
    const __nv_bfloat16* A = xb;
    const __nv_bfloat16* W = (sel == 0) ? wq : (sel == 1) ? wk : wv;
    const float* bias      = (sel == 0) ? bq : (sel == 1) ? bk : bv;
    __nv_bfloat16* C       = (sel == 0) ? qb : (sel == 1) ? kb : vb;

    const int tid  = threadIdx.x;
    const int lane = tid & 31;
    const int wid  = tid >> 5;
    const int wm   = (wid >> 2) * 64;
    const int wn   = (wid & 3) * 32;
    const int g    = lane >> 2;
    const int c    = lane & 3;

    float acc[4][4][4];
    #pragma unroll
    for (int i = 0; i < 4; i++)
        #pragma unroll
        for (int j = 0; j < 4; j++)
            #pragma unroll
            for (int r = 0; r < 4; r++) acc[i][j][r] = 0.f;

    const int idx0 = tid * 2;
    const int r0   = idx0 >> 2;
    const int h0   = (idx0 & 3) << 3;
    const int idx1 = idx0 + 1;
    const int r1   = idx1 >> 2;
    const int h1   = (idx1 & 3) << 3;

    const unsigned sA = (unsigned)__cvta_generic_to_shared(qsm);
    const unsigned sB = sA + 3 * QKV_STG;

    auto load_tile = [&](int st, int k0) {
        CP_ASYNC16(sA + st * QKV_STG + (r0 * 40 + h0) * 2, &A[(size_t)(m0 + r0) * 256 + k0 + h0]);
        CP_ASYNC16(sB + st * QKV_STG + (r0 * 40 + h0) * 2, &W[(size_t)(n0 + r0) * 256 + k0 + h0]);
        CP_ASYNC16(sA + st * QKV_STG + (r1 * 40 + h1) * 2, &A[(size_t)(m0 + r1) * 256 + k0 + h1]);
        CP_ASYNC16(sB + st * QKV_STG + (r1 * 40 + h1) * 2, &W[(size_t)(n0 + r1) * 256 + k0 + h1]);
    };

    const int arow = lane & 15;
    const int acol = (lane >> 4) << 3;
    const int brow = (lane & 7) + ((lane >> 4) << 3);
    const int bcol = ((lane >> 3) & 1) << 3;

    load_tile(0, 0);  CP_COMMIT();
    load_tile(1, 32); CP_COMMIT();

    #pragma unroll
    for (int kt = 0; kt < 8; kt++) {
        const int st = kt % 3;
        if (kt == 7) { CP_WAIT(0); } else { CP_WAIT(1); }
        __syncthreads();
        if (kt + 2 < 8) { load_tile((kt + 2) % 3, (kt + 2) * 32); CP_COMMIT(); }

        #pragma unroll
        for (int kk = 0; kk < 2; kk++) {
            const int kb = kk * 16;
            unsigned af[4][4];
            unsigned bf[4][2];
            #pragma unroll
            for (int im = 0; im < 4; im++) {
                unsigned addr = sA + st * QKV_STG +
                    (unsigned)(((wm + im * 16 + arow) * 40 + kb + acol) * 2);
                LDSM_X4(af[im][0], af[im][1], af[im][2], af[im][3], addr);
            }
            #pragma unroll
            for (int np = 0; np < 2; np++) {
                unsigned addr = sB + st * QKV_STG +
                    (unsigned)(((wn + np * 16 + brow) * 40 + kb + bcol) * 2);
                LDSM_X4(bf[2 * np][0], bf[2 * np][1], bf[2 * np + 1][0], bf[2 * np + 1][1], addr);
            }
            #pragma unroll
            for (int im = 0; im < 4; im++)
                #pragma unroll
                for (int in_ = 0; in_ < 4; in_++)
                    mma_bf16(acc[im][in_], af[im], bf[in_]);
        }
    }

    #pragma unroll
    for (int im = 0; im < 4; im++) {
        int row = m0 + wm + im * 16 + g;
        #pragma unroll
        for (int in_ = 0; in_ < 4; in_++) {
            int col = n0 + wn + in_ * 8 + 2 * c;
            float b0 = bias[col], b1 = bias[col + 1];
            *(__nv_bfloat162*)&C[(size_t)row * 256 + col] =
                __float22bfloat162_rn(make_float2(acc[im][in_][0] + b0, acc[im][in_][1] + b1));
            *(__nv_bfloat162*)&C[(size_t)(row + 8) * 256 + col] =
                __float22bfloat162_rn(make_float2(acc[im][in_][2] + b0, acc[im][in_][3] + b1));
        }
    }
}

// ----------------------------------------------------------------------------
// Fused FC GEMM + residual + LayerNorm v2: 3-stage cp.async, single sync/iter.
// BM=128, BN=256, BK=16. Tile buffers in dynamic smem (3 stages, 55296 B).
// ----------------------------------------------------------------------------
#define FSTR 24
#define FC_ASTG (128 * FSTR * 2)          // 6144
#define FC_BSTG (256 * FSTR * 2)          // 12288
#define FC_SMEM (3 * (FC_ASTG + FC_BSTG)) // 55296

__global__ __launch_bounds__(256) void gemm_fc_ln_kernel(
    const __nv_bfloat16* __restrict__ A, const __nv_bfloat16* __restrict__ W,
    const float* __restrict__ bias, const float* __restrict__ x,
    const float* __restrict__ gamma, const float* __restrict__ beta,
    float* __restrict__ out)
{
    extern __shared__ __nv_bfloat16 fsm[];
    __shared__ float psum[8][64];
    __shared__ float psum2[8][64];
    __shared__ float smu[128];
    __shared__ float srstd[128];

    const int tid  = threadIdx.x;
    const int lane = tid & 31;
    const int wid  = tid >> 5;
    const int wm   = (wid >> 2) * 64;
    const int wn   = (wid & 3) * 64;
    const int m0   = blockIdx.x * 128;
    const int g    = lane >> 2;
    const int c    = lane & 3;

    float acc[4][8][4];
    #pragma unroll
    for (int i = 0; i < 4; i++)
        #pragma unroll
        for (int j = 0; j < 8; j++)
            #pragma unroll
            for (int r = 0; r < 4; r++) acc[i][j][r] = 0.f;

    const int rA = tid >> 1;
    const int cC = (tid & 1) << 3;

    const unsigned sA = (unsigned)__cvta_generic_to_shared(fsm);
    const unsigned sB = sA + 3 * FC_ASTG;

    auto load_tile = [&](int st, int k0) {
        CP_ASYNC16(sA + st * FC_ASTG + (rA * FSTR + cC) * 2,
                   &A[(size_t)(m0 + rA) * 256 + k0 + cC]);
        CP_ASYNC16(sB + st * FC_BSTG + (rA * FSTR + cC) * 2,
                   &W[(size_t)rA * 256 + k0 + cC]);
        CP_ASYNC16(sB + st * FC_BSTG + ((128 + rA) * FSTR + cC) * 2,
                   &W[(size_t)(128 + rA) * 256 + k0 + cC]);
    };

    const int arow = lane & 15;
    const int acol = (lane >> 4) << 3;
    const int brow = (lane & 7) + ((lane >> 4) << 3);
    const int bcol = ((lane >> 3) & 1) << 3;

    load_tile(0, 0);  CP_COMMIT();
    load_tile(1, 16); CP_COMMIT();

    #pragma unroll
    for (int kt = 0; kt < 16; kt++) {
        const int st = kt % 3;
        if (kt == 15) { CP_WAIT(0); } else { CP_WAIT(1); }
        __syncthreads();
        // load into stage (kt+2)%3 == (kt-1)%3: its consumers finished compute
        // of iter kt-1 before this barrier. Single sync per iteration.
        if (kt + 2 < 16) { load_tile((kt + 2) % 3, (kt + 2) * 16); CP_COMMIT(); }

        unsigned af[4][4];
        unsigned bf[8][2];
        #pragma unroll
        for (int im = 0; im < 4; im++) {
            unsigned addr = sA + st * FC_ASTG +
                (unsigned)(((wm + im * 16 + arow) * FSTR + acol) * 2);
            LDSM_X4(af[im][0], af[im][1], af[im][2], af[im][3], addr);
        }
        #pragma unroll
        for (int np = 0; np < 4; np++) {
            unsigned addr = sB + st * FC_BSTG +
                (unsigned)(((wn + np * 16 + brow) * FSTR + bcol) * 2);
            LDSM_X4(bf[2 * np][0], bf[2 * np][1], bf[2 * np + 1][0], bf[2 * np + 1][1], addr);
        }
        #pragma unroll
        for (int im = 0; im < 4; im++)
            #pragma unroll
            for (int in_ = 0; in_ < 8; in_++)
                mma_bf16(acc[im][in_], af[im], bf[in_]);
    }

    #pragma unroll
    for (int im = 0; im < 4; im++) {
        size_t row  = (size_t)(m0 + wm + im * 16 + g) * 256;
        size_t row2 = row + 8 * 256;
        float s1 = 0.f, q1 = 0.f, s2 = 0.f, q2 = 0.f;
        #pragma unroll
        for (int in_ = 0; in_ < 8; in_++) {
            int col = wn + in_ * 8 + 2 * c;
            float b0 = bias[col], b1 = bias[col + 1];
            float2 x0 = *(const float2*)&x[row + col];
            float2 x1 = *(const float2*)&x[row2 + col];
            float v00 = acc[im][in_][0] + b0 + x0.x;
            float v01 = acc[im][in_][1] + b1 + x0.y;
            float v10 = acc[im][in_][2] + b0 + x1.x;
            float v11 = acc[im][in_][3] + b1 + x1.y;
            acc[im][in_][0] = v00; acc[im][in_][1] = v01;
            acc[im][in_][2] = v10; acc[im][in_][3] = v11;
            s1 += v00 + v01; q1 += v00 * v00 + v01 * v01;
            s2 += v10 + v11; q2 += v10 * v10 + v11 * v11;
        }
        #pragma unroll
        for (int off = 1; off <= 2; off <<= 1) {
            s1 += __shfl_xor_sync(0xffffffffu, s1, off);
            q1 += __shfl_xor_sync(0xffffffffu, q1, off);
            s2 += __shfl_xor_sync(0xffffffffu, s2, off);
            q2 += __shfl_xor_sync(0xffffffffu, q2, off);
        }
        if (c == 0) {
            psum[wid][im * 16 + g]      = s1;
            psum2[wid][im * 16 + g]     = q1;
            psum[wid][im * 16 + g + 8]  = s2;
            psum2[wid][im * 16 + g + 8] = q2;
        }
    }
    __syncthreads();

    if (tid < 128) {
        const int half = tid >> 6;
        const int ri   = tid & 63;
        float s = 0.f, q = 0.f;
        #pragma unroll
        for (int j = 0; j < 4; j++) {
            s += psum[half * 4 + j][ri];
            q += psum2[half * 4 + j][ri];
        }
        float mu  = s * (1.f / 256.f);
        float var = q * (1.f / 256.f) - mu * mu;
        smu[tid]   = mu;
        srstd[tid] = rsqrtf(var + 1e-5f);
    }
    __syncthreads();

    #pragma unroll
    for (int im = 0; im < 4; im++) {
        int rl = wm + im * 16 + g;
        float mu1 = smu[rl],     rs1 = srstd[rl];
        float mu2 = smu[rl + 8], rs2 = srstd[rl + 8];
        size_t row  = (size_t)(m0 + rl) * 256;
        size_t row2 = row + 8 * 256;
        #pragma unroll
        for (int in_ = 0; in_ < 8; in_++) {
            int col = wn + in_ * 8 + 2 * c;
            float ga0 = gamma[col], ga1 = gamma[col + 1];
            float be0 = beta[col],  be1 = beta[col + 1];
            *(float2*)&out[row + col] = make_float2(
                (acc[im][in_][0] - mu1) * rs1 * ga0 + be0,
                (acc[im][in_][1] - mu1) * rs1 * ga1 + be1);
            *(float2*)&out[row2 + col] = make_float2(
                (acc[im][in_][2] - mu2) * rs2 * ga0 + be0,
                (acc[im][in_][3] - mu2) * rs2 * ga1 + be1);
        }
    }
}

// ----------------------------------------------------------------------------
// Attention v6 (R12/R13, proven): all-bf16, all fragments via ldmatrix.
// ----------------------------------------------------------------------------
#define ASTR 264
#define P_STR 40
#define ATTN_SMEM ((80 * ASTR + Hh * 16 * P_STR) * 2)   // 52480 bytes

__global__ __launch_bounds__(256) void attn_kernel(
    const __nv_bfloat16* __restrict__ Q, const __nv_bfloat16* __restrict__ K,
    const __nv_bfloat16* __restrict__ V,
    const float* __restrict__ mem_k, const float* __restrict__ mem_v,
    const float* __restrict__ alpha_l, __nv_bfloat16* __restrict__ out)
{
    extern __shared__ __nv_bfloat16 smem_attn[];
    __nv_bfloat16* Qs = smem_attn;
    __nv_bfloat16* Ks = smem_attn + 16 * ASTR;
    __nv_bfloat16* Vc = smem_attn + 48 * ASTR;

    const int tid  = threadIdx.x;
    const int lane = tid & 31;
    const int h    = tid >> 5;
    const int g    = lane >> 2;
    const int c    = lane & 3;
    const int hc   = h * DK;
    const size_t base = (size_t)blockIdx.x * (Tt * Dd);

    __nv_bfloat16* Ph = smem_attn + 80 * ASTR + h * (16 * P_STR);

    for (int i = tid; i < Tt * 32; i += 256) {
        int r = i >> 5, c8 = (i & 31) * 8;
        *(uint4*)&Qs[r * ASTR + c8] = *(const uint4*)&Q[base + r * 256 + c8];
        *(uint4*)&Ks[r * ASTR + c8] = *(const uint4*)&K[base + r * 256 + c8];
        *(uint4*)&Vc[r * ASTR + c8] = *(const uint4*)&V[base + r * 256 + c8];
    }
    {
        const uint4 z4 = make_uint4(0u, 0u, 0u, 0u);
        for (int i = tid; i < 28 * 32; i += 256) {
            int rr = i >> 5, c8 = (i & 31) * 8;
            __nv_bfloat16* dst;
            int row;
            if (rr < 4)       { dst = Qs; row = 12 + rr; }
            else if (rr < 8)  { dst = Ks; row = 12 + (rr - 4); }
            else if (rr < 16) { dst = Ks; row = 24 + (rr - 8); }
            else if (rr < 20) { dst = Vc; row = 12 + (rr - 16); }
            else              { dst = Vc; row = 24 + (rr - 20); }
            *(uint4*)&dst[row * ASTR + c8] = z4;
        }
    }
    #pragma unroll
    for (int m = 0; m < Mm; m++) {
        Ks[(16 + m) * ASTR + hc + lane] =
            __float2bfloat16_rn(mem_k[(h * Mm + m) * DK + lane]);
        Vc[(16 + m) * ASTR + hc + lane] =
            __float2bfloat16_rn(mem_v[(h * Mm + m) * DK + lane]);
    }
    {
        uint32_t* pz = (uint32_t*)Ph;
        #pragma unroll
        for (int i = 0; i < 10; i++) pz[lane + i * 32] = 0u;
    }
    __syncthreads();

    const unsigned sQ = (unsigned)__cvta_generic_to_shared(Qs);
    const unsigned sK = (unsigned)__cvta_generic_to_shared(Ks);
    const unsigned sV = (unsigned)__cvta_generic_to_shared(Vc);
    const unsigned sP = (unsigned)__cvta_generic_to_shared(Ph);

    const int arow = lane & 15;
    const int acol = (lane >> 4) << 3;
    const int brow = (lane & 7) + ((lane >> 4) << 3);
    const int bcol = ((lane >> 3) & 1) << 3;
    const int trow = ((lane >> 3) & 1) * 8 + (lane & 7);
    const int tcol = (lane >> 4) << 3;

    float s0[4] = {0.f, 0.f, 0.f, 0.f};
    float s1[4] = {0.f, 0.f, 0.f, 0.f};
    float sm_[4] = {0.f, 0.f, 0.f, 0.f};
    #pragma unroll
    for (int kk = 0; kk < 2; kk++) {
        const int kb = hc + kk * 16;
        unsigned a[4], b01[4], bm[4];
        LDSM_X4(a[0], a[1], a[2], a[3],
                sQ + (unsigned)((arow * ASTR + kb + acol) * 2));
        LDSM_X4(b01[0], b01[1], b01[2], b01[3],
                sK + (unsigned)((brow * ASTR + kb + bcol) * 2));
        LDSM_X4(bm[0], bm[1], bm[2], bm[3],
                sK + (unsigned)(((16 + brow) * ASTR + kb + bcol) * 2));
        mma_bf16(s0, a, &b01[0]);
        mma_bf16(s1, a, &b01[2]);
        mma_bf16(sm_, a, &bm[0]);
    }

    const float scale = 0.1767766952966369f;
    const int s00 = 2 * c, s01 = 2 * c + 1, s10 = 8 + 2 * c, s11 = 8 + 2 * c + 1;
    const int tlo = g, thi = g + 8;
    float e[8];
    e[0] = (s00 <= tlo) ? s0[0] * scale : -1e30f;
    e[1] = (s01 <= tlo) ? s0[1] * scale : -1e30f;
    e[2] = (s10 <= tlo) ? s1[0] * scale : -1e30f;
    e[3] = (s11 <= tlo) ? s1[1] * scale : -1e30f;
    e[4] = (s00 <= thi) ? s0[2] * scale : -1e30f;
    e[5] = (s01 <= thi) ? s0[3] * scale : -1e30f;
    e[6] = (s10 <= thi) ? s1[2] * scale : -1e30f;
    e[7] = (s11 <= thi) ? s1[3] * scale : -1e30f;

    float mlo = fmaxf(fmaxf(e[0], e[1]), fmaxf(e[2], e[3]));
    float mhi = fmaxf(fmaxf(e[4], e[5]), fmaxf(e[6], e[7]));
    mlo = fmaxf(mlo, __shfl_xor_sync(0xffffffffu, mlo, 1));
    mlo = fmaxf(mlo, __shfl_xor_sync(0xffffffffu, mlo, 2));
    mhi = fmaxf(mhi, __shfl_xor_sync(0xffffffffu, mhi, 1));
    mhi = fmaxf(mhi, __shfl_xor_sync(0xffffffffu, mhi, 2));
    #pragma unroll
    for (int j = 0; j < 4; j++) e[j] = __expf(e[j] - mlo);
    #pragma unroll
    for (int j = 4; j < 8; j++) e[j] = __expf(e[j] - mhi);
    float slo = e[0] + e[1] + e[2] + e[3];
    float shi = e[4] + e[5] + e[6] + e[7];
    slo += __shfl_xor_sync(0xffffffffu, slo, 1);
    slo += __shfl_xor_sync(0xffffffffu, slo, 2);
    shi += __shfl_xor_sync(0xffffffffu, shi, 1);
    shi += __shfl_xor_sync(0xffffffffu, shi, 2);
    float rlo = 1.f / slo, rhi = 1.f / shi;
    #pragma unroll
    for (int j = 0; j < 4; j++) e[j] *= rlo;
    #pragma unroll
    for (int j = 4; j < 8; j++) e[j] *= rhi;

    float em[4];
    em[0] = sm_[0] * scale; em[1] = sm_[1] * scale;
    em[2] = sm_[2] * scale; em[3] = sm_[3] * scale;
    float mmlo = fmaxf(em[0], em[1]);
    float mmhi = fmaxf(em[2], em[3]);
    mmlo = fmaxf(mmlo, __shfl_xor_sync(0xffffffffu, mmlo, 1));
    mmlo = fmaxf(mmlo, __shfl_xor_sync(0xffffffffu, mmlo, 2));
    mmhi = fmaxf(mmhi, __shfl_xor_sync(0xffffffffu, mmhi, 1));
    mmhi = fmaxf(mmhi, __shfl_xor_sync(0xffffffffu, mmhi, 2));
    em[0] = __expf(em[0] - mmlo); em[1] = __expf(em[1] - mmlo);
    em[2] = __expf(em[2] - mmhi); em[3] = __expf(em[3] - mmhi);
    float smlo = em[0] + em[1];
    float smhi = em[2] + em[3];
    smlo += __shfl_xor_sync(0xffffffffu, smlo, 1);
    smlo += __shfl_xor_sync(0xffffffffu, smlo, 2);
    smhi += __shfl_xor_sync(0xffffffffu, smhi, 1);
    smhi += __shfl_xor_sync(0xffffffffu, smhi, 2);
    em[0] *= 1.f / smlo; em[1] *= 1.f / smlo;
    em[2] *= 1.f / smhi; em[3] *= 1.f / smhi;

    const float wl = 1.f / (1.f + __expf(-alpha_l[0]));
    const float wt = 1.f - wl;
    Ph[tlo * P_STR + s00] = __float2bfloat16_rn(wt * e[0]);
    Ph[tlo * P_STR + s01] = __float2bfloat16_rn(wt * e[1]);
    Ph[tlo * P_STR + s10] = __float2bfloat16_rn(wt * e[2]);
    Ph[tlo * P_STR + s11] = __float2bfloat16_rn(wt * e[3]);
    Ph[tlo * P_STR + 16 + s00] = __float2bfloat16_rn(wl * em[0]);
    Ph[tlo * P_STR + 16 + s01] = __float2bfloat16_rn(wl * em[1]);
    if (g < 4) {
        Ph[thi * P_STR + s00] = __float2bfloat16_rn(wt * e[4]);
        Ph[thi * P_STR + s01] = __float2bfloat16_rn(wt * e[5]);
        Ph[thi * P_STR + s10] = __float2bfloat16_rn(wt * e[6]);
        Ph[thi * P_STR + s11] = __float2bfloat16_rn(wt * e[7]);
        Ph[thi * P_STR + 16 + s00] = __float2bfloat16_rn(wl * em[2]);
        Ph[thi * P_STR + 16 + s01] = __float2bfloat16_rn(wl * em[3]);
    }
    __syncwarp();

    float o[4][4];
    #pragma unroll
    for (int nt = 0; nt < 4; nt++)
        #pragma unroll
        for (int r = 0; r < 4; r++) o[nt][r] = 0.f;

    #pragma unroll
    for (int kk = 0; kk < 2; kk++) {
        const int kb = kk * 16;
        unsigned pa[4];
        LDSM_X4(pa[0], pa[1], pa[2], pa[3],
                sP + (unsigned)((arow * P_STR + kb + acol) * 2));
        #pragma unroll
        for (int pair = 0; pair < 2; pair++) {
            unsigned vr[4];
            LDSM_X4_T(vr[0], vr[1], vr[2], vr[3],
                      sV + (unsigned)(((kb + trow) * ASTR + hc + pair * 16 + tcol) * 2));
            mma_bf16(o[pair * 2],     pa, &vr[0]);
            mma_bf16(o[pair * 2 + 1], pa, &vr[2]);
        }
    }

    #pragma unroll
    for (int nt = 0; nt < 4; nt++) {
        int col = hc + nt * 8 + 2 * c;
        *(__nv_bfloat162*)&out[base + tlo * 256 + col] =
            __float22bfloat162_rn(make_float2(o[nt][0], o[nt][1]));
        if (g < 4) {
            *(__nv_bfloat162*)&out[base + thi * 256 + col] =
                __float22bfloat162_rn(make_float2(o[nt][2], o[nt][3]));
        }
    }
}

// ----------------------------------------------------------------------------
// Launch
// ----------------------------------------------------------------------------
extern "C" void kernel_launch(void* const* d_in, const int* in_sizes, int n_in,
                              void* d_out, int out_size)
{
    const float* x     = (const float*)d_in[0];
    const float* Wq_w  = (const float*)d_in[1];
    const float* Wq_b  = (const float*)d_in[2];
    const float* Wk_w  = (const float*)d_in[3];
    const float* Wk_b  = (const float*)d_in[4];
    const float* Wv_w  = (const float*)d_in[5];
    const float* Wv_b  = (const float*)d_in[6];
    const float* mem_k = (const float*)d_in[7];
    const float* mem_v = (const float*)d_in[8];
    const float* fc_w  = (const float*)d_in[9];
    const float* fc_b  = (const float*)d_in[10];
    const float* gamma = (const float*)d_in[11];
    const float* beta  = (const float*)d_in[12];
    const float* alpha = (const float*)d_in[13];
    float* out = (float*)d_out;

    __nv_bfloat16 *xb, *qb, *kb, *vb, *ab, *wq, *wk, *wv, *wf;
    cudaGetSymbolAddress((void**)&xb, g_xb);
    cudaGetSymbolAddress((void**)&qb, g_qb);
    cudaGetSymbolAddress((void**)&kb, g_kb);
    cudaGetSymbolAddress((void**)&vb, g_vb);
    cudaGetSymbolAddress((void**)&ab, g_ab);
    cudaGetSymbolAddress((void**)&wq, g_wq);
    cudaGetSymbolAddress((void**)&wk, g_wk);
    cudaGetSymbolAddress((void**)&wv, g_wv);
    cudaGetSymbolAddress((void**)&wf, g_wf);

    cudaFuncSetAttribute(attn_kernel,
                         cudaFuncAttributeMaxDynamicSharedMemorySize, ATTN_SMEM);
    cudaFuncSetAttribute(gemm_qkv_kernel,
                         cudaFuncAttributeMaxDynamicSharedMemorySize, QKV_SMEM);
    cudaFuncSetAttribute(gemm_fc_ln_kernel,
                         cudaFuncAttributeMaxDynamicSharedMemorySize, FC_SMEM);

    const int xn4 = ROWS * Dd / 4;
    cvt_kernel<<<(xn4 + 255) / 256, 256>>>(x, xb, xn4);
    dim3 wgrid(64, 4);
    cvt_w_kernel<<<wgrid, 256>>>(Wq_w, Wk_w, Wv_w, fc_w, wq, wk, wv, wf);

    dim3 qkv_grid(6, ROWS / 128);
    gemm_qkv_kernel<<<qkv_grid, 256, QKV_SMEM>>>(
        xb, wq, wk, wv, Wq_b, Wk_b, Wv_b, qb, kb, vb);

    attn_kernel<<<BN_CNT, 256, ATTN_SMEM>>>(qb, kb, vb, mem_k, mem_v, alpha, ab);

    gemm_fc_ln_kernel<<<ROWS / 128, 256, FC_SMEM>>>(ab, wf, fc_b, x, gamma, beta, out);
}

// round 15
// speedup vs baseline: 1.3240x; 1.0066x over previous
#include <cuda_runtime.h>
#include <cuda_bf16.h>
#include <math.h>
#include <stdint.h>

#define Bb 8
#define Nn 2048
#define Tt 12
#define Dd 256
#define Hh 8
#define DK 32
#define Mm 8
#define ROWS (Bb * Nn * Tt)          // 196608
#define BN_CNT (Bb * Nn)             // 16384

// Scratch (device globals; allocation-free rule)
__device__ __nv_bfloat16 g_xb[ROWS * Dd];
__device__ __nv_bfloat16 g_qb[ROWS * Dd];
__device__ __nv_bfloat16 g_kb[ROWS * Dd];
__device__ __nv_bfloat16 g_vb[ROWS * Dd];
__device__ __nv_bfloat16 g_ab[ROWS * Dd];
__device__ __nv_bfloat16 g_wq[Dd * Dd];
__device__ __nv_bfloat16 g_wk[Dd * Dd];
__device__ __nv_bfloat16 g_wv[Dd * Dd];
__device__ __nv_bfloat16 g_wf[Dd * Dd];

#define CP_ASYNC16(dst, src) \
    asm volatile("cp.async.cg.shared.global [%0], [%1], 16;" :: "r"(dst), "l"(src))
#define CP_COMMIT() asm volatile("cp.async.commit_group;")
#define CP_WAIT(n)  asm volatile("cp.async.wait_group %0;" :: "n"(n))

#define LDSM_X4(r0, r1, r2, r3, addr) \
    asm volatile("ldmatrix.sync.aligned.m8n8.x4.shared.b16 {%0,%1,%2,%3}, [%4];" \
        : "=r"(r0), "=r"(r1), "=r"(r2), "=r"(r3) : "r"(addr))

#define LDSM_X4_T(r0, r1, r2, r3, addr) \
    asm volatile("ldmatrix.sync.aligned.m8n8.x4.trans.shared.b16 {%0,%1,%2,%3}, [%4];" \
        : "=r"(r0), "=r"(r1), "=r"(r2), "=r"(r3) : "r"(addr))

__device__ __forceinline__ void mma_bf16(float* c, const unsigned* a, const unsigned* b) {
    asm volatile(
        "mma.sync.aligned.m16n8k16.row.col.f32.bf16.bf16.f32 "
        "{%0,%1,%2,%3}, {%4,%5,%6,%7}, {%8,%9}, {%0,%1,%2,%3};"
        : "+f"(c[0]), "+f"(c[1]), "+f"(c[2]), "+f"(c[3])
        : "r"(a[0]), "r"(a[1]), "r"(a[2]), "r"(a[3]), "r"(b[0]), "r"(b[1]));
}

// ----------------------------------------------------------------------------
// fp32 -> bf16 conversions
// ----------------------------------------------------------------------------
__global__ __launch_bounds__(256) void cvt_kernel(
    const float* __restrict__ in, __nv_bfloat16* __restrict__ out, int n4)
{
    int i = blockIdx.x * 256 + threadIdx.x;
    if (i < n4) {
        float4 v = ((const float4*)in)[i];
        ((__nv_bfloat162*)out)[2 * i]     = __float22bfloat162_rn(make_float2(v.x, v.y));
        ((__nv_bfloat162*)out)[2 * i + 1] = __float22bfloat162_rn(make_float2(v.z, v.w));
    }
}

__global__ __launch_bounds__(256) void cvt_w_kernel(
    const float* __restrict__ w0, const float* __restrict__ w1,
    const float* __restrict__ w2, const float* __restrict__ w3,
    __nv_bfloat16* __restrict__ d0, __nv_bfloat16* __restrict__ d1,
    __nv_bfloat16* __restrict__ d2, __nv_bfloat16* __restrict__ d3)
{
    const int sel = blockIdx.y;
    const float* in = (sel == 0) ? w0 : (sel == 1) ? w1 : (sel == 2) ? w2 : w3;
    __nv_bfloat16* out = (sel == 0) ? d0 : (sel == 1) ? d1 : (sel == 2) ? d2 : d3;
    int i = blockIdx.x * 256 + threadIdx.x;
    float4 v = ((const float4*)in)[i];
    ((__nv_bfloat162*)out)[2 * i]     = __float22bfloat162_rn(make_float2(v.x, v.y));
    ((__nv_bfloat162*)out)[2 * i + 1] = __float22bfloat162_rn(make_float2(v.z, v.w));
}

// ----------------------------------------------------------------------------
// QKV GEMM v3 (R13, proven): BM=BN=128, BK=32, 3-stage cp.async, single sync.
// grid = (6, ROWS/128): consecutive CTA ids share one A tile -> A hits L2.
// ----------------------------------------------------------------------------
#define QKV_STG (128 * 40 * 2)
#define QKV_SMEM (6 * QKV_STG)          // 61440

__global__ __launch_bounds__(256) void gemm_qkv_kernel(
    const __nv_bfloat16* __restrict__ xb,
    const __nv_bfloat16* __restrict__ wq, const __nv_bfloat16* __restrict__ wk,
    const __nv_bfloat16* __restrict__ wv,
    const float* __restrict__ bq, const float* __restrict__ bk,
    const float* __restrict__ bv,
    __nv_bfloat16* __restrict__ qb, __nv_bfloat16* __restrict__ kb,
    __nv_bfloat16* __restrict__ vb)
{
    extern __shared__ __nv_bfloat16 qsm[];

    const int sel = blockIdx.x >> 1;
    const int n0  = (blockIdx.x & 1) * 128;
    const int m0  = blockIdx.y * 128;
    const __nv_bfloat16* A = xb;
    const __nv_bfloat16* W = (sel == 0) ? wq : (sel == 1) ? wk : wv;
    const float* bias      = (sel == 0) ? bq : (sel == 1) ? bk : bv;
    __nv_bfloat16* C       = (sel == 0) ? qb : (sel == 1) ? kb : vb;

    const int tid  = threadIdx.x;
    const int lane = tid & 31;
    const int wid  = tid >> 5;
    const int wm   = (wid >> 2) * 64;
    const int wn   = (wid & 3) * 32;
    const int g    = lane >> 2;
    const int c    = lane & 3;

    float acc[4][4][4];
    #pragma unroll
    for (int i = 0; i < 4; i++)
        #pragma unroll
        for (int j = 0; j < 4; j++)
            #pragma unroll
            for (int r = 0; r < 4; r++) acc[i][j][r] = 0.f;

    const int idx0 = tid * 2;
    const int r0   = idx0 >> 2;
    const int h0   = (idx0 & 3) << 3;
    const int idx1 = idx0 + 1;
    const int r1   = idx1 >> 2;
    const int h1   = (idx1 & 3) << 3;

    const unsigned sA = (unsigned)__cvta_generic_to_shared(qsm);
    const unsigned sB = sA + 3 * QKV_STG;

    auto load_tile = [&](int st, int k0) {
        CP_ASYNC16(sA + st * QKV_STG + (r0 * 40 + h0) * 2, &A[(size_t)(m0 + r0) * 256 + k0 + h0]);
        CP_ASYNC16(sB + st * QKV_STG + (r0 * 40 + h0) * 2, &W[(size_t)(n0 + r0) * 256 + k0 + h0]);
        CP_ASYNC16(sA + st * QKV_STG + (r1 * 40 + h1) * 2, &A[(size_t)(m0 + r1) * 256 + k0 + h1]);
        CP_ASYNC16(sB + st * QKV_STG + (r1 * 40 + h1) * 2, &W[(size_t)(n0 + r1) * 256 + k0 + h1]);
    };

    const int arow = lane & 15;
    const int acol = (lane >> 4) << 3;
    const int brow = (lane & 7) + ((lane >> 4) << 3);
    const int bcol = ((lane >> 3) & 1) << 3;

    load_tile(0, 0);  CP_COMMIT();
    load_tile(1, 32); CP_COMMIT();

    #pragma unroll
    for (int kt = 0; kt < 8; kt++) {
        const int st = kt % 3;
        if (kt == 7) { CP_WAIT(0); } else { CP_WAIT(1); }
        __syncthreads();
        if (kt + 2 < 8) { load_tile((kt + 2) % 3, (kt + 2) * 32); CP_COMMIT(); }

        #pragma unroll
        for (int kk = 0; kk < 2; kk++) {
            const int kb = kk * 16;
            unsigned af[4][4];
            unsigned bf[4][2];
            #pragma unroll
            for (int im = 0; im < 4; im++) {
                unsigned addr = sA + st * QKV_STG +
                    (unsigned)(((wm + im * 16 + arow) * 40 + kb + acol) * 2);
                LDSM_X4(af[im][0], af[im][1], af[im][2], af[im][3], addr);
            }
            #pragma unroll
            for (int np = 0; np < 2; np++) {
                unsigned addr = sB + st * QKV_STG +
                    (unsigned)(((wn + np * 16 + brow) * 40 + kb + bcol) * 2);
                LDSM_X4(bf[2 * np][0], bf[2 * np][1], bf[2 * np + 1][0], bf[2 * np + 1][1], addr);
            }
            #pragma unroll
            for (int im = 0; im < 4; im++)
                #pragma unroll
                for (int in_ = 0; in_ < 4; in_++)
                    mma_bf16(acc[im][in_], af[im], bf[in_]);
        }
    }

    #pragma unroll
    for (int im = 0; im < 4; im++) {
        int row = m0 + wm + im * 16 + g;
        #pragma unroll
        for (int in_ = 0; in_ < 4; in_++) {
            int col = n0 + wn + in_ * 8 + 2 * c;
            float b0 = bias[col], b1 = bias[col + 1];
            *(__nv_bfloat162*)&C[(size_t)row * 256 + col] =
                __float22bfloat162_rn(make_float2(acc[im][in_][0] + b0, acc[im][in_][1] + b1));
            *(__nv_bfloat162*)&C[(size_t)(row + 8) * 256 + col] =
                __float22bfloat162_rn(make_float2(acc[im][in_][2] + b0, acc[im][in_][3] + b1));
        }
    }
}

// ----------------------------------------------------------------------------
// Fused FC GEMM + residual + LayerNorm v2 (R14, proven): 3-stage, single sync.
// ----------------------------------------------------------------------------
#define FSTR 24
#define FC_ASTG (128 * FSTR * 2)
#define FC_BSTG (256 * FSTR * 2)
#define FC_SMEM (3 * (FC_ASTG + FC_BSTG)) // 55296

__global__ __launch_bounds__(256) void gemm_fc_ln_kernel(
    const __nv_bfloat16* __restrict__ A, const __nv_bfloat16* __restrict__ W,
    const float* __restrict__ bias, const float* __restrict__ x,
    const float* __restrict__ gamma, const float* __restrict__ beta,
    float* __restrict__ out)
{
    extern __shared__ __nv_bfloat16 fsm[];
    __shared__ float psum[8][64];
    __shared__ float psum2[8][64];
    __shared__ float smu[128];
    __shared__ float srstd[128];

    const int tid  = threadIdx.x;
    const int lane = tid & 31;
    const int wid  = tid >> 5;
    const int wm   = (wid >> 2) * 64;
    const int wn   = (wid & 3) * 64;
    const int m0   = blockIdx.x * 128;
    const int g    = lane >> 2;
    const int c    = lane & 3;

    float acc[4][8][4];
    #pragma unroll
    for (int i = 0; i < 4; i++)
        #pragma unroll
        for (int j = 0; j < 8; j++)
            #pragma unroll
            for (int r = 0; r < 4; r++) acc[i][j][r] = 0.f;

    const int rA = tid >> 1;
    const int cC = (tid & 1) << 3;

    const unsigned sA = (unsigned)__cvta_generic_to_shared(fsm);
    const unsigned sB = sA + 3 * FC_ASTG;

    auto load_tile = [&](int st, int k0) {
        CP_ASYNC16(sA + st * FC_ASTG + (rA * FSTR + cC) * 2,
                   &A[(size_t)(m0 + rA) * 256 + k0 + cC]);
        CP_ASYNC16(sB + st * FC_BSTG + (rA * FSTR + cC) * 2,
                   &W[(size_t)rA * 256 + k0 + cC]);
        CP_ASYNC16(sB + st * FC_BSTG + ((128 + rA) * FSTR + cC) * 2,
                   &W[(size_t)(128 + rA) * 256 + k0 + cC]);
    };

    const int arow = lane & 15;
    const int acol = (lane >> 4) << 3;
    const int brow = (lane & 7) + ((lane >> 4) << 3);
    const int bcol = ((lane >> 3) & 1) << 3;

    load_tile(0, 0);  CP_COMMIT();
    load_tile(1, 16); CP_COMMIT();

    #pragma unroll
    for (int kt = 0; kt < 16; kt++) {
        const int st = kt % 3;
        if (kt == 15) { CP_WAIT(0); } else { CP_WAIT(1); }
        __syncthreads();
        if (kt + 2 < 16) { load_tile((kt + 2) % 3, (kt + 2) * 16); CP_COMMIT(); }

        unsigned af[4][4];
        unsigned bf[8][2];
        #pragma unroll
        for (int im = 0; im < 4; im++) {
            unsigned addr = sA + st * FC_ASTG +
                (unsigned)(((wm + im * 16 + arow) * FSTR + acol) * 2);
            LDSM_X4(af[im][0], af[im][1], af[im][2], af[im][3], addr);
        }
        #pragma unroll
        for (int np = 0; np < 4; np++) {
            unsigned addr = sB + st * FC_BSTG +
                (unsigned)(((wn + np * 16 + brow) * FSTR + bcol) * 2);
            LDSM_X4(bf[2 * np][0], bf[2 * np][1], bf[2 * np + 1][0], bf[2 * np + 1][1], addr);
        }
        #pragma unroll
        for (int im = 0; im < 4; im++)
            #pragma unroll
            for (int in_ = 0; in_ < 8; in_++)
                mma_bf16(acc[im][in_], af[im], bf[in_]);
    }

    #pragma unroll
    for (int im = 0; im < 4; im++) {
        size_t row  = (size_t)(m0 + wm + im * 16 + g) * 256;
        size_t row2 = row + 8 * 256;
        float s1 = 0.f, q1 = 0.f, s2 = 0.f, q2 = 0.f;
        #pragma unroll
        for (int in_ = 0; in_ < 8; in_++) {
            int col = wn + in_ * 8 + 2 * c;
            float b0 = bias[col], b1 = bias[col + 1];
            float2 x0 = *(const float2*)&x[row + col];
            float2 x1 = *(const float2*)&x[row2 + col];
            float v00 = acc[im][in_][0] + b0 + x0.x;
            float v01 = acc[im][in_][1] + b1 + x0.y;
            float v10 = acc[im][in_][2] + b0 + x1.x;
            float v11 = acc[im][in_][3] + b1 + x1.y;
            acc[im][in_][0] = v00; acc[im][in_][1] = v01;
            acc[im][in_][2] = v10; acc[im][in_][3] = v11;
            s1 += v00 + v01; q1 += v00 * v00 + v01 * v01;
            s2 += v10 + v11; q2 += v10 * v10 + v11 * v11;
        }
        #pragma unroll
        for (int off = 1; off <= 2; off <<= 1) {
            s1 += __shfl_xor_sync(0xffffffffu, s1, off);
            q1 += __shfl_xor_sync(0xffffffffu, q1, off);
            s2 += __shfl_xor_sync(0xffffffffu, s2, off);
            q2 += __shfl_xor_sync(0xffffffffu, q2, off);
        }
        if (c == 0) {
            psum[wid][im * 16 + g]      = s1;
            psum2[wid][im * 16 + g]     = q1;
            psum[wid][im * 16 + g + 8]  = s2;
            psum2[wid][im * 16 + g + 8] = q2;
        }
    }
    __syncthreads();

    if (tid < 128) {
        const int half = tid >> 6;
        const int ri   = tid & 63;
        float s = 0.f, q = 0.f;
        #pragma unroll
        for (int j = 0; j < 4; j++) {
            s += psum[half * 4 + j][ri];
            q += psum2[half * 4 + j][ri];
        }
        float mu  = s * (1.f / 256.f);
        float var = q * (1.f / 256.f) - mu * mu;
        smu[tid]   = mu;
        srstd[tid] = rsqrtf(var + 1e-5f);
    }
    __syncthreads();

    #pragma unroll
    for (int im = 0; im < 4; im++) {
        int rl = wm + im * 16 + g;
        float mu1 = smu[rl],     rs1 = srstd[rl];
        float mu2 = smu[rl + 8], rs2 = srstd[rl + 8];
        size_t row  = (size_t)(m0 + rl) * 256;
        size_t row2 = row + 8 * 256;
        #pragma unroll
        for (int in_ = 0; in_ < 8; in_++) {
            int col = wn + in_ * 8 + 2 * c;
            float ga0 = gamma[col], ga1 = gamma[col + 1];
            float be0 = beta[col],  be1 = beta[col + 1];
            *(float2*)&out[row + col] = make_float2(
                (acc[im][in_][0] - mu1) * rs1 * ga0 + be0,
                (acc[im][in_][1] - mu1) * rs1 * ga1 + be1);
            *(float2*)&out[row2 + col] = make_float2(
                (acc[im][in_][2] - mu2) * rs2 * ga0 + be0,
                (acc[im][in_][3] - mu2) * rs2 * ga1 + be1);
        }
    }
}

// ----------------------------------------------------------------------------
// Attention v7: P written INTO Qs (cols h*32..h*32+31) after scores -> smem
// drops 52.5KB -> 41.3KB -> 5 CTAs/SM. Full 16x32 P block explicitly defined
// (masked-zero time cols, zero stores for cols 24..31, g>=4 lanes zero rows
// 12..15). Otherwise identical to proven R12-R14 attention.
// ----------------------------------------------------------------------------
#define ASTR 264
#define ATTN_SMEM (80 * ASTR * 2)   // 42240 bytes

__global__ __launch_bounds__(256) void attn_kernel(
    const __nv_bfloat16* __restrict__ Q, const __nv_bfloat16* __restrict__ K,
    const __nv_bfloat16* __restrict__ V,
    const float* __restrict__ mem_k, const float* __restrict__ mem_v,
    const float* __restrict__ alpha_l, __nv_bfloat16* __restrict__ out)
{
    extern __shared__ __nv_bfloat16 smem_attn[];
    __nv_bfloat16* Qs = smem_attn;              // 16 rows (reused for P)
    __nv_bfloat16* Ks = smem_attn + 16 * ASTR;  // 32 rows
    __nv_bfloat16* Vc = smem_attn + 48 * ASTR;  // 32 rows

    const int tid  = threadIdx.x;
    const int lane = tid & 31;
    const int h    = tid >> 5;
    const int g    = lane >> 2;
    const int c    = lane & 3;
    const int hc   = h * DK;
    const size_t base = (size_t)blockIdx.x * (Tt * Dd);

    __nv_bfloat16* Ph = Qs + hc;   // P lives in Qs' own head columns

    for (int i = tid; i < Tt * 32; i += 256) {
        int r = i >> 5, c8 = (i & 31) * 8;
        *(uint4*)&Qs[r * ASTR + c8] = *(const uint4*)&Q[base + r * 256 + c8];
        *(uint4*)&Ks[r * ASTR + c8] = *(const uint4*)&K[base + r * 256 + c8];
        *(uint4*)&Vc[r * ASTR + c8] = *(const uint4*)&V[base + r * 256 + c8];
    }
    {
        const uint4 z4 = make_uint4(0u, 0u, 0u, 0u);
        for (int i = tid; i < 28 * 32; i += 256) {
            int rr = i >> 5, c8 = (i & 31) * 8;
            __nv_bfloat16* dst;
            int row;
            if (rr < 4)       { dst = Qs; row = 12 + rr; }
            else if (rr < 8)  { dst = Ks; row = 12 + (rr - 4); }
            else if (rr < 16) { dst = Ks; row = 24 + (rr - 8); }
            else if (rr < 20) { dst = Vc; row = 12 + (rr - 16); }
            else              { dst = Vc; row = 24 + (rr - 20); }
            *(uint4*)&dst[row * ASTR + c8] = z4;
        }
    }
    #pragma unroll
    for (int m = 0; m < Mm; m++) {
        Ks[(16 + m) * ASTR + hc + lane] =
            __float2bfloat16_rn(mem_k[(h * Mm + m) * DK + lane]);
        Vc[(16 + m) * ASTR + hc + lane] =
            __float2bfloat16_rn(mem_v[(h * Mm + m) * DK + lane]);
    }
    __syncthreads();

    const unsigned sQ = (unsigned)__cvta_generic_to_shared(Qs);
    const unsigned sK = (unsigned)__cvta_generic_to_shared(Ks);
    const unsigned sV = (unsigned)__cvta_generic_to_shared(Vc);

    const int arow = lane & 15;
    const int acol = (lane >> 4) << 3;
    const int brow = (lane & 7) + ((lane >> 4) << 3);
    const int bcol = ((lane >> 3) & 1) << 3;
    const int trow = ((lane >> 3) & 1) * 8 + (lane & 7);
    const int tcol = (lane >> 4) << 3;

    float s0[4] = {0.f, 0.f, 0.f, 0.f};
    float s1[4] = {0.f, 0.f, 0.f, 0.f};
    float sm_[4] = {0.f, 0.f, 0.f, 0.f};
    #pragma unroll
    for (int kk = 0; kk < 2; kk++) {
        const int kb = hc + kk * 16;
        unsigned a[4], b01[4], bm[4];
        LDSM_X4(a[0], a[1], a[2], a[3],
                sQ + (unsigned)((arow * ASTR + kb + acol) * 2));
        LDSM_X4(b01[0], b01[1], b01[2], b01[3],
                sK + (unsigned)((brow * ASTR + kb + bcol) * 2));
        LDSM_X4(bm[0], bm[1], bm[2], bm[3],
                sK + (unsigned)(((16 + brow) * ASTR + kb + bcol) * 2));
        mma_bf16(s0, a, &b01[0]);
        mma_bf16(s1, a, &b01[2]);
        mma_bf16(sm_, a, &bm[0]);
    }

    const float scale = 0.1767766952966369f;
    const int s00 = 2 * c, s01 = 2 * c + 1, s10 = 8 + 2 * c, s11 = 8 + 2 * c + 1;
    const int tlo = g, thi = g + 8;
    float e[8];
    e[0] = (s00 <= tlo) ? s0[0] * scale : -1e30f;
    e[1] = (s01 <= tlo) ? s0[1] * scale : -1e30f;
    e[2] = (s10 <= tlo) ? s1[0] * scale : -1e30f;
    e[3] = (s11 <= tlo) ? s1[1] * scale : -1e30f;
    e[4] = (s00 <= thi) ? s0[2] * scale : -1e30f;
    e[5] = (s01 <= thi) ? s0[3] * scale : -1e30f;
    e[6] = (s10 <= thi) ? s1[2] * scale : -1e30f;
    e[7] = (s11 <= thi) ? s1[3] * scale : -1e30f;

    float mlo = fmaxf(fmaxf(e[0], e[1]), fmaxf(e[2], e[3]));
    float mhi = fmaxf(fmaxf(e[4], e[5]), fmaxf(e[6], e[7]));
    mlo = fmaxf(mlo, __shfl_xor_sync(0xffffffffu, mlo, 1));
    mlo = fmaxf(mlo, __shfl_xor_sync(0xffffffffu, mlo, 2));
    mhi = fmaxf(mhi, __shfl_xor_sync(0xffffffffu, mhi, 1));
    mhi = fmaxf(mhi, __shfl_xor_sync(0xffffffffu, mhi, 2));
    #pragma unroll
    for (int j = 0; j < 4; j++) e[j] = __expf(e[j] - mlo);
    #pragma unroll
    for (int j = 4; j < 8; j++) e[j] = __expf(e[j] - mhi);
    float slo = e[0] + e[1] + e[2] + e[3];
    float shi = e[4] + e[5] + e[6] + e[7];
    slo += __shfl_xor_sync(0xffffffffu, slo, 1);
    slo += __shfl_xor_sync(0xffffffffu, slo, 2);
    shi += __shfl_xor_sync(0xffffffffu, shi, 1);
    shi += __shfl_xor_sync(0xffffffffu, shi, 2);
    float rlo = 1.f / slo, rhi = 1.f / shi;
    #pragma unroll
    for (int j = 0; j < 4; j++) e[j] *= rlo;
    #pragma unroll
    for (int j = 4; j < 8; j++) e[j] *= rhi;

    float em[4];
    em[0] = sm_[0] * scale; em[1] = sm_[1] * scale;
    em[2] = sm_[2] * scale; em[3] = sm_[3] * scale;
    float mmlo = fmaxf(em[0], em[1]);
    float mmhi = fmaxf(em[2], em[3]);
    mmlo = fmaxf(mmlo, __shfl_xor_sync(0xffffffffu, mmlo, 1));
    mmlo = fmaxf(mmlo, __shfl_xor_sync(0xffffffffu, mmlo, 2));
    mmhi = fmaxf(mmhi, __shfl_xor_sync(0xffffffffu, mmhi, 1));
    mmhi = fmaxf(mmhi, __shfl_xor_sync(0xffffffffu, mmhi, 2));
    em[0] = __expf(em[0] - mmlo); em[1] = __expf(em[1] - mmlo);
    em[2] = __expf(em[2] - mmhi); em[3] = __expf(em[3] - mmhi);
    float smlo = em[0] + em[1];
    float smhi = em[2] + em[3];
    smlo += __shfl_xor_sync(0xffffffffu, smlo, 1);
    smlo += __shfl_xor_sync(0xffffffffu, smlo, 2);
    smhi += __shfl_xor_sync(0xffffffffu, smhi, 1);
    smhi += __shfl_xor_sync(0xffffffffu, smhi, 2);
    em[0] *= 1.f / smlo; em[1] *= 1.f / smlo;
    em[2] *= 1.f / smhi; em[3] *= 1.f / smhi;

    // ---- write gate-scaled P into Qs head slice; define full 16x32 block ----
    const float wl = 1.f / (1.f + __expf(-alpha_l[0]));
    const float wt = 1.f - wl;
    // row tlo (0..7): time (masked entries already exactly 0), mem, zero 24..31
    *(__nv_bfloat162*)&Ph[tlo * ASTR + s00] =
        __float22bfloat162_rn(make_float2(wt * e[0], wt * e[1]));
    *(__nv_bfloat162*)&Ph[tlo * ASTR + s10] =
        __float22bfloat162_rn(make_float2(wt * e[2], wt * e[3]));
    *(__nv_bfloat162*)&Ph[tlo * ASTR + 16 + s00] =
        __float22bfloat162_rn(make_float2(wl * em[0], wl * em[1]));
    *(uint32_t*)&Ph[tlo * ASTR + 24 + 2 * c] = 0u;
    if (g < 4) {
        // row thi (8..11): values
        *(__nv_bfloat162*)&Ph[thi * ASTR + s00] =
            __float22bfloat162_rn(make_float2(wt * e[4], wt * e[5]));
        *(__nv_bfloat162*)&Ph[thi * ASTR + s10] =
            __float22bfloat162_rn(make_float2(wt * e[6], wt * e[7]));
        *(__nv_bfloat162*)&Ph[thi * ASTR + 16 + s00] =
            __float22bfloat162_rn(make_float2(wl * em[2], wl * em[3]));
        *(uint32_t*)&Ph[thi * ASTR + 24 + 2 * c] = 0u;
    } else {
        // row thi (12..15): all zero (discarded output rows; keeps MMA NaN-free)
        *(uint32_t*)&Ph[thi * ASTR + 2 * c]      = 0u;
        *(uint32_t*)&Ph[thi * ASTR + 8 + 2 * c]  = 0u;
        *(uint32_t*)&Ph[thi * ASTR + 16 + 2 * c] = 0u;
        *(uint32_t*)&Ph[thi * ASTR + 24 + 2 * c] = 0u;
    }
    __syncwarp();

    float o[4][4];
    #pragma unroll
    for (int nt = 0; nt < 4; nt++)
        #pragma unroll
        for (int r = 0; r < 4; r++) o[nt][r] = 0.f;

    #pragma unroll
    for (int kk = 0; kk < 2; kk++) {
        const int kb = kk * 16;
        unsigned pa[4];
        LDSM_X4(pa[0], pa[1], pa[2], pa[3],
                sQ + (unsigned)((arow * ASTR + hc + kb + acol) * 2));
        #pragma unroll
        for (int pair = 0; pair < 2; pair++) {
            unsigned vr[4];
            LDSM_X4_T(vr[0], vr[1], vr[2], vr[3],
                      sV + (unsigned)(((kb + trow) * ASTR + hc + pair * 16 + tcol) * 2));
            mma_bf16(o[pair * 2],     pa, &vr[0]);
            mma_bf16(o[pair * 2 + 1], pa, &vr[2]);
        }
    }

    #pragma unroll
    for (int nt = 0; nt < 4; nt++) {
        int col = hc + nt * 8 + 2 * c;
        *(__nv_bfloat162*)&out[base + tlo * 256 + col] =
            __float22bfloat162_rn(make_float2(o[nt][0], o[nt][1]));
        if (g < 4) {
            *(__nv_bfloat162*)&out[base + thi * 256 + col] =
                __float22bfloat162_rn(make_float2(o[nt][2], o[nt][3]));
        }
    }
}

// ----------------------------------------------------------------------------
// Launch
// ----------------------------------------------------------------------------
extern "C" void kernel_launch(void* const* d_in, const int* in_sizes, int n_in,
                              void* d_out, int out_size)
{
    const float* x     = (const float*)d_in[0];
    const float* Wq_w  = (const float*)d_in[1];
    const float* Wq_b  = (const float*)d_in[2];
    const float* Wk_w  = (const float*)d_in[3];
    const float* Wk_b  = (const float*)d_in[4];
    const float* Wv_w  = (const float*)d_in[5];
    const float* Wv_b  = (const float*)d_in[6];
    const float* mem_k = (const float*)d_in[7];
    const float* mem_v = (const float*)d_in[8];
    const float* fc_w  = (const float*)d_in[9];
    const float* fc_b  = (const float*)d_in[10];
    const float* gamma = (const float*)d_in[11];
    const float* beta  = (const float*)d_in[12];
    const float* alpha = (const float*)d_in[13];
    float* out = (float*)d_out;

    __nv_bfloat16 *xb, *qb, *kb, *vb, *ab, *wq, *wk, *wv, *wf;
    cudaGetSymbolAddress((void**)&xb, g_xb);
    cudaGetSymbolAddress((void**)&qb, g_qb);
    cudaGetSymbolAddress((void**)&kb, g_kb);
    cudaGetSymbolAddress((void**)&vb, g_vb);
    cudaGetSymbolAddress((void**)&ab, g_ab);
    cudaGetSymbolAddress((void**)&wq, g_wq);
    cudaGetSymbolAddress((void**)&wk, g_wk);
    cudaGetSymbolAddress((void**)&wv, g_wv);
    cudaGetSymbolAddress((void**)&wf, g_wf);

    cudaFuncSetAttribute(attn_kernel,
                         cudaFuncAttributeMaxDynamicSharedMemorySize, ATTN_SMEM);
    cudaFuncSetAttribute(gemm_qkv_kernel,
                         cudaFuncAttributeMaxDynamicSharedMemorySize, QKV_SMEM);
    cudaFuncSetAttribute(gemm_fc_ln_kernel,
                         cudaFuncAttributeMaxDynamicSharedMemorySize, FC_SMEM);

    const int xn4 = ROWS * Dd / 4;
    cvt_kernel<<<(xn4 + 255) / 256, 256>>>(x, xb, xn4);
    dim3 wgrid(64, 4);
    cvt_w_kernel<<<wgrid, 256>>>(Wq_w, Wk_w, Wv_w, fc_w, wq, wk, wv, wf);

    dim3 qkv_grid(6, ROWS / 128);
    gemm_qkv_kernel<<<qkv_grid, 256, QKV_SMEM>>>(
        xb, wq, wk, wv, Wq_b, Wk_b, Wv_b, qb, kb, vb);

    attn_kernel<<<BN_CNT, 256, ATTN_SMEM>>>(qb, kb, vb, mem_k, mem_v, alpha, ab);

    gemm_fc_ln_kernel<<<ROWS / 128, 256, FC_SMEM>>>(ab, wf, fc_b, x, gamma, beta, out);
}